// round 7
// baseline (speedup 1.0000x reference)
#include <cuda_runtime.h>
#include <cuda_bf16.h>

// ---------------------------------------------------------------------------
// WeightedTP via warp-level mma.sync (HMMA):
//   tp = A[2048 x 65*272] @ Wsym[65*272 x 128],  A[n,(k,j)] = h[n,k]*c[n,j]
// bf16 hi/lo 3-term split (AhBh + AhBl + AlBh), fp32 accumulate.
// R7: tp 512 threads (16 warps, 32x32 warp tile) + B prefetch;
//     bfrag fused (w2 -> B-fragments directly); cfrag smem-staged;
//     out_kernel 16 rows/block.
// ---------------------------------------------------------------------------

#define MAXN 2048
#define NK 65            // 64 hidden + bias row (h=1)
#define NJ 272           // 17 chunks of 16
#define NJC 17
#define KSPLIT 9

#define PATH_COEFF 0.04419417382415922f
#define CG110      0.57735026918962576f
#define LN_EPS     1e-5f

__device__ float g_hT[64 * MAXN];                    // [k][n]
__device__ float g_c[MAXN * NJ];                     // [n][j]
__device__ uint4 g_bf[(size_t)NK * NJC * 16 * 32];   // B frags [k][jc][wt][lane]
__device__ float4 g_cf[(size_t)(MAXN/16) * NJC * 32 * 2]; // c frags [mt][jc][lane][2]
__device__ float g_tp[(size_t)KSPLIT * MAXN * 128];

__device__ __forceinline__ float silu_f(float v) { return v / (1.0f + __expf(-v)); }

// split fp32 pair into bf16x2 hi + bf16x2 lo (a0 -> low half)
__device__ __forceinline__ void split2(float a0, float a1, unsigned& hi, unsigned& lo) {
    unsigned h;
    asm("cvt.rn.bf16x2.f32 %0, %1, %2;" : "=r"(h) : "f"(a1), "f"(a0));
    float h0 = __uint_as_float(h << 16);
    float h1 = __uint_as_float(h & 0xFFFF0000u);
    float r0 = a0 - h0, r1 = a1 - h1;
    asm("cvt.rn.bf16x2.f32 %0, %1, %2;" : "=r"(lo) : "f"(r1), "f"(r0));
    hi = h;
}

__device__ __forceinline__ void mma16816(float* d, const unsigned* a,
                                         unsigned b0, unsigned b1) {
    asm volatile(
        "mma.sync.aligned.m16n8k16.row.col.f32.bf16.bf16.f32 "
        "{%0,%1,%2,%3}, {%4,%5,%6,%7}, {%8,%9}, {%0,%1,%2,%3};"
        : "+f"(d[0]), "+f"(d[1]), "+f"(d[2]), "+f"(d[3])
        : "r"(a[0]), "r"(a[1]), "r"(a[2]), "r"(a[3]), "r"(b0), "r"(b1));
}

// ---------------------------------------------------------------------------
// Kernel 1: fused symmetrize + pack into mma B-fragment layout (bf16 hi/lo).
// One thread per uint4: (k, jc, wt, lane); reads we_w2/we_b2 directly.
// lane: w = wt*8 + (lane>>2); j0 = jc*16 + (lane&3)*2; vals j0,j0+1,j0+8,j0+9.
// ---------------------------------------------------------------------------
__device__ __forceinline__ float wsym_val(const float* __restrict__ w2,
                                          const float* __restrict__ b2,
                                          int k, int j, int w) {
    int p = j / 136, q = j % 136, u = 0;
    while (q >= 16 - u) { q -= 16 - u; u++; }
    int v = u + q;
    const float* src = (k < 64) ? (w2 + (size_t)k * 65536) : b2;
    float val = src[((p * 256 + u * 16 + v) << 7) + w];
    if (u != v) val += src[((p * 256 + v * 16 + u) << 7) + w];
    return val;
}

__global__ void bfrag_kernel(const float* __restrict__ w2,
                             const float* __restrict__ b2) {
    int idx = blockIdx.x * blockDim.x + threadIdx.x;
    const int total = NK * NJC * 16 * 32;
    if (idx >= total) return;
    int lane = idx & 31;
    int wt   = (idx >> 5) & 15;
    int rest = idx >> 9;
    int jc   = rest % NJC;
    int k    = rest / NJC;
    int w  = wt * 8 + (lane >> 2);
    int j0 = jc * 16 + (lane & 3) * 2;
    float v0 = wsym_val(w2, b2, k, j0,     w);
    float v1 = wsym_val(w2, b2, k, j0 + 1, w);
    float v2 = wsym_val(w2, b2, k, j0 + 8, w);
    float v3 = wsym_val(w2, b2, k, j0 + 9, w);
    uint4 o;
    split2(v0, v1, o.x, o.z);
    split2(v2, v3, o.y, o.w);
    g_bf[idx] = o;
}

// ---------------------------------------------------------------------------
// Kernel 2: per-row prep — h (transposed [k][n]), c ([n][j]).
// ---------------------------------------------------------------------------
__global__ void prep_kernel(const float* __restrict__ x,
                            const float* __restrict__ lng,
                            const float* __restrict__ lnb,
                            const float* __restrict__ w1, int N) {
    __shared__ float xs[8][64];
    __shared__ float lns[8][16];
    int warp = threadIdx.x >> 5;
    int lane = threadIdx.x & 31;
    int n = blockIdx.x * 8 + warp;
    if (n >= N) return;

    xs[warp][lane]      = x[(size_t)n * 64 + lane];
    xs[warp][lane + 32] = x[(size_t)n * 64 + 32 + lane];
    __syncwarp();

    float f = (lane < 16) ? xs[warp][lane] : 0.0f;
    float s = f;
    #pragma unroll
    for (int o = 16; o; o >>= 1) s += __shfl_xor_sync(0xffffffffu, s, o);
    float mu = s * (1.0f / 16.0f);
    float d = (lane < 16) ? (f - mu) : 0.0f;
    float ss = d * d;
    #pragma unroll
    for (int o = 16; o; o >>= 1) ss += __shfl_xor_sync(0xffffffffu, ss, o);
    float rstd = rsqrtf(ss * (1.0f / 16.0f) + LN_EPS);
    if (lane < 16) lns[warp][lane] = d * rstd * lng[lane] + lnb[lane];
    __syncwarp();

    #pragma unroll
    for (int t = 0; t < 2; t++) {
        int j = lane + 32 * t;
        float acc = 0.0f;
        #pragma unroll
        for (int i = 0; i < 16; i++) acc += lns[warp][i] * w1[i * 64 + j];
        g_hT[(size_t)j * MAXN + n] = silu_f(acc);
    }

    for (int t = lane; t < NJ; t += 32) {
        int p = t / 136, q = t % 136, u = 0;
        while (q >= 16 - u) { q -= 16 - u; u++; }
        int v = u + q;
        float val;
        if (p == 0) {
            val = PATH_COEFF * xs[warp][u] * xs[warp][v];
        } else {
            const float* a = &xs[warp][16 + u * 3];
            const float* b = &xs[warp][16 + v * 3];
            val = PATH_COEFF * CG110 * (a[0] * b[0] + a[1] * b[1] + a[2] * b[2]);
        }
        g_c[(size_t)n * NJ + t] = val;
    }
}

// ---------------------------------------------------------------------------
// Kernel 2b: pack c into A-fragment-ordered fp32 quads, smem-staged.
// One block per 16-row m-tile; coalesced loads and stores.
// ---------------------------------------------------------------------------
__global__ __launch_bounds__(256) void cfrag_kernel(int N) {
    __shared__ float cs[16 * NJ];
    int tid = threadIdx.x;
    int mt = blockIdx.x;
    for (int s = tid; s < 16 * NJ; s += 256)
        cs[s] = g_c[(size_t)mt * 16 * NJ + s];
    __syncthreads();
    for (int t = tid; t < NJC * 32; t += 256) {
        int lane = t & 31;
        int jc = t >> 5;
        int ra = lane >> 2;
        int j0 = jc * 16 + (lane & 3) * 2;
        const float* c0 = cs + ra * NJ;
        const float* c8 = c0 + 8 * NJ;
        float4 f0, f1;
        f0.x = c0[j0];     f0.y = c0[j0 + 1]; f0.z = c8[j0];     f0.w = c8[j0 + 1];
        f1.x = c0[j0 + 8]; f1.y = c0[j0 + 9]; f1.z = c8[j0 + 8]; f1.w = c8[j0 + 9];
        size_t o = ((size_t)(mt * NJC + jc) * 32 + lane) * 2;
        g_cf[o] = f0;
        g_cf[o + 1] = f1;
    }
}

// ---------------------------------------------------------------------------
// Kernel 3: HMMA contraction. Grid (N/128, KSPLIT), 512 threads (16 warps).
// Warp = (mw = wid>>2: 32 rows, nh = wid&3: 32 w-cols). acc[2 mtl][4 wt][4].
// B prefetched one k-step ahead.
// ---------------------------------------------------------------------------
__global__ __launch_bounds__(512, 1) void tp_kernel(int N) {
    __shared__ float h_sm[8 * 128];
    int tid = threadIdx.x;
    int warp = tid >> 5;
    int lane = tid & 31;
    int mblk = blockIdx.x;
    int base = mblk * 128;
    int split = blockIdx.y;
    int k0 = (split * NK) / KSPLIT;
    int k1 = ((split + 1) * NK) / KSPLIT;
    int kc = k1 - k0;

    for (int s = tid; s < kc * 128; s += 512) {
        int k = k0 + (s >> 7);
        h_sm[s] = (k == 64) ? 1.0f : g_hT[(size_t)k * MAXN + base + (s & 127)];
    }
    __syncthreads();

    int mw = warp >> 2;
    int nh = warp & 3;
    int ra = lane >> 2;
    int qb = lane & 3;

    float acc[2][4][4];
    #pragma unroll
    for (int a = 0; a < 2; a++)
        #pragma unroll
        for (int b = 0; b < 4; b++)
            #pragma unroll
            for (int cdx = 0; cdx < 4; cdx++) acc[a][b][cdx] = 0.0f;

    const size_t kstride = (size_t)NJC * 16 * 32;

    for (int jc = 0; jc < NJC; jc++) {
        float4 cf[2][2];
        #pragma unroll
        for (int mtl = 0; mtl < 2; mtl++) {
            int mt = mblk * 8 + mw * 2 + mtl;
            size_t o = ((size_t)(mt * NJC + jc) * 32 + lane) * 2;
            cf[mtl][0] = g_cf[o];
            cf[mtl][1] = g_cf[o + 1];
        }
        const uint4* bp = g_bf + (((size_t)k0 * NJC + jc) * 16 + nh * 4) * 32 + lane;
        uint4 bb[4];
        #pragma unroll
        for (int wt = 0; wt < 4; wt++) bb[wt] = bp[(size_t)wt * 32];

        for (int kk = 0; kk < kc; kk++) {
            uint4 bn[4];
            if (kk + 1 < kc) {
                const uint4* bq = bp + (size_t)(kk + 1) * kstride;
                #pragma unroll
                for (int wt = 0; wt < 4; wt++) bn[wt] = bq[(size_t)wt * 32];
            }
            unsigned ah[2][4], al[2][4];
            #pragma unroll
            for (int mtl = 0; mtl < 2; mtl++) {
                int r0 = mw * 32 + mtl * 16 + ra;
                float h0 = h_sm[kk * 128 + r0];
                float h1 = h_sm[kk * 128 + r0 + 8];
                split2(h0 * cf[mtl][0].x, h0 * cf[mtl][0].y, ah[mtl][0], al[mtl][0]);
                split2(h1 * cf[mtl][0].z, h1 * cf[mtl][0].w, ah[mtl][1], al[mtl][1]);
                split2(h0 * cf[mtl][1].x, h0 * cf[mtl][1].y, ah[mtl][2], al[mtl][2]);
                split2(h1 * cf[mtl][1].z, h1 * cf[mtl][1].w, ah[mtl][3], al[mtl][3]);
            }
            #pragma unroll
            for (int wt = 0; wt < 4; wt++) {
                mma16816(acc[0][wt], ah[0], bb[wt].x, bb[wt].y);   // Ah*Bh
                mma16816(acc[1][wt], ah[1], bb[wt].x, bb[wt].y);
                mma16816(acc[0][wt], ah[0], bb[wt].z, bb[wt].w);   // Ah*Bl
                mma16816(acc[1][wt], ah[1], bb[wt].z, bb[wt].w);
                mma16816(acc[0][wt], al[0], bb[wt].x, bb[wt].y);   // Al*Bh
                mma16816(acc[1][wt], al[1], bb[wt].x, bb[wt].y);
            }
            if (kk + 1 < kc) {
                #pragma unroll
                for (int wt = 0; wt < 4; wt++) bb[wt] = bn[wt];
            }
        }
    }

    // D layout: d0,d1 = (row ra, col 2qb,2qb+1); d2,d3 = row ra+8.
    #pragma unroll
    for (int mtl = 0; mtl < 2; mtl++) {
        int r0 = base + mw * 32 + mtl * 16 + ra;
        #pragma unroll
        for (int wt = 0; wt < 4; wt++) {
            int col = nh * 32 + wt * 8 + 2 * qb;
            float2* p0 = reinterpret_cast<float2*>(
                g_tp + ((size_t)split * N + r0) * 128 + col);
            float2* p1 = reinterpret_cast<float2*>(
                g_tp + ((size_t)split * N + r0 + 8) * 128 + col);
            *p0 = make_float2(acc[mtl][wt][0], acc[mtl][wt][1]);
            *p1 = make_float2(acc[mtl][wt][2], acc[mtl][wt][3]);
        }
    }
}

// ---------------------------------------------------------------------------
// Kernel 4: epilogue — sum splits, LN(128), silu(@om_w1), @om_w2 + b.
// 16 rows per 256-thread block; thread-halves each own 8 rows.
// ---------------------------------------------------------------------------
__global__ __launch_bounds__(256) void out_kernel(const float* __restrict__ lng,
                                                  const float* __restrict__ lnb,
                                                  const float* __restrict__ w1,
                                                  const float* __restrict__ w2,
                                                  const float* __restrict__ bias2,
                                                  float* __restrict__ out, int N) {
    __shared__ float ln_sm[16][128];
    __shared__ float part_sm[16][128];
    int tid = threadIdx.x, lane = tid & 31, warp = tid >> 5;
    int rowbase = blockIdx.x * 16;

    // Phase A: 2 rows per warp — sum 9 splits + LayerNorm
    #pragma unroll
    for (int rr = 0; rr < 2; rr++) {
        int r = warp * 2 + rr;
        int g = rowbase + r;
        float v[4];
        #pragma unroll
        for (int t = 0; t < 4; t++) {
            int i = lane + 32 * t;
            float s = 0.0f;
            #pragma unroll
            for (int sp = 0; sp < KSPLIT; sp++)
                s += g_tp[((size_t)sp * N + g) * 128 + i];
            v[t] = s;
        }
        float s = v[0] + v[1] + v[2] + v[3];
        #pragma unroll
        for (int o = 16; o; o >>= 1) s += __shfl_xor_sync(0xffffffffu, s, o);
        float mu = s * (1.0f / 128.0f);
        float ss = 0.0f;
        #pragma unroll
        for (int t = 0; t < 4; t++) { float d = v[t] - mu; ss += d * d; }
        #pragma unroll
        for (int o = 16; o; o >>= 1) ss += __shfl_xor_sync(0xffffffffu, ss, o);
        float rstd = rsqrtf(ss * (1.0f / 128.0f) + LN_EPS);
        #pragma unroll
        for (int t = 0; t < 4; t++) {
            int i = lane + 32 * t;
            ln_sm[r][i] = (v[t] - mu) * rstd * lng[i] + lnb[i];
        }
    }
    __syncthreads();

    // Phase B: thread-half hf owns rows hf*8..hf*8+7; q = 4 w1 columns
    int q = tid & 127, hf = tid >> 7;
    float y[8][4];
    #pragma unroll
    for (int r = 0; r < 8; r++)
        #pragma unroll
        for (int cdx = 0; cdx < 4; cdx++) y[r][cdx] = 0.0f;

    const float4* w1v = reinterpret_cast<const float4*>(w1);
    #pragma unroll 4
    for (int i = 0; i < 128; i++) {
        float4 wv = w1v[i * 128 + q];
        #pragma unroll
        for (int r = 0; r < 8; r++) {
            float l = ln_sm[hf * 8 + r][i];
            y[r][0] += l * wv.x;
            y[r][1] += l * wv.y;
            y[r][2] += l * wv.z;
            y[r][3] += l * wv.w;
        }
    }
    float4 w2v = reinterpret_cast<const float4*>(w2)[q];
    #pragma unroll
    for (int r = 0; r < 8; r++) {
        part_sm[hf * 8 + r][q] =
            silu_f(y[r][0]) * w2v.x + silu_f(y[r][1]) * w2v.y +
            silu_f(y[r][2]) * w2v.z + silu_f(y[r][3]) * w2v.w;
    }
    __syncthreads();

    // 2 rows per warp reduce
    #pragma unroll
    for (int rr = 0; rr < 2; rr++) {
        int r = warp * 2 + rr;
        float s = part_sm[r][lane] + part_sm[r][lane + 32] +
                  part_sm[r][lane + 64] + part_sm[r][lane + 96];
        #pragma unroll
        for (int o = 16; o; o >>= 1) s += __shfl_xor_sync(0xffffffffu, s, o);
        if (lane == 0) out[rowbase + r] = s + bias2[0];
    }
}

// ---------------------------------------------------------------------------
extern "C" void kernel_launch(void* const* d_in, const int* in_sizes, int n_in,
                              void* d_out, int out_size) {
    const float* x        = (const float*)d_in[0];
    const float* we_ln_g  = (const float*)d_in[1];
    const float* we_ln_b  = (const float*)d_in[2];
    const float* we_w1    = (const float*)d_in[3];
    const float* we_w2    = (const float*)d_in[4];
    const float* we_b2    = (const float*)d_in[5];
    const float* om_ln_g  = (const float*)d_in[6];
    const float* om_ln_b  = (const float*)d_in[7];
    const float* om_w1    = (const float*)d_in[8];
    const float* om_w2    = (const float*)d_in[9];
    const float* om_b2    = (const float*)d_in[10];

    int N = in_sizes[0] / 64;
    if (N > MAXN) N = MAXN;

    const int totalF = NK * NJC * 16 * 32;

    bfrag_kernel<<<(totalF + 255) / 256, 256>>>(we_w2, we_b2);
    prep_kernel<<<(N + 7) / 8, 256>>>(x, we_ln_g, we_ln_b, we_w1, N);
    cfrag_kernel<<<N / 16, 256>>>(N);
    tp_kernel<<<dim3(N / 128, KSPLIT), 512>>>(N);
    out_kernel<<<N / 16, 256>>>(om_ln_g, om_ln_b, om_w1, om_w2, om_b2,
                                (float*)d_out, N);
}

// round 8
// speedup vs baseline: 1.2320x; 1.2320x over previous
#include <cuda_runtime.h>
#include <cuda_bf16.h>

// ---------------------------------------------------------------------------
// WeightedTP via warp-level mma.sync (HMMA):
//   tp = A[2048 x 65*272] @ Wsym[65*272 x 128],  A[n,(k,j)] = h[n,k]*c[n,j]
// bf16 hi/lo 3-term split (AhBh + AhBl + AlBh), fp32 accumulate.
// R8: R6 tile (8 warps, warp 32x64, 96 HMMA/iter) + KSPLIT=18 (288 CTAs,
//     2 CTA/SM via launch_bounds(256,2)); cfrag fused into prep.
// ---------------------------------------------------------------------------

#define MAXN 2048
#define NK 65            // 64 hidden + bias row (h=1)
#define NJ 272           // 17 chunks of 16
#define NJC 17
#define KSPLIT 18

#define PATH_COEFF 0.04419417382415922f
#define CG110      0.57735026918962576f
#define LN_EPS     1e-5f

__device__ float g_hT[64 * MAXN];                    // [k][n]
__device__ uint4 g_bf[(size_t)NK * NJC * 16 * 32];   // B frags [k][jc][wt][lane]
__device__ float4 g_cf[(size_t)(MAXN/16) * NJC * 32 * 2]; // c frags [mt][jc][lane][2]
__device__ float g_tp[(size_t)KSPLIT * MAXN * 128];

__device__ __forceinline__ float silu_f(float v) { return v / (1.0f + __expf(-v)); }

// split fp32 pair into bf16x2 hi + bf16x2 lo (a0 -> low half)
__device__ __forceinline__ void split2(float a0, float a1, unsigned& hi, unsigned& lo) {
    unsigned h;
    asm("cvt.rn.bf16x2.f32 %0, %1, %2;" : "=r"(h) : "f"(a1), "f"(a0));
    float h0 = __uint_as_float(h << 16);
    float h1 = __uint_as_float(h & 0xFFFF0000u);
    float r0 = a0 - h0, r1 = a1 - h1;
    asm("cvt.rn.bf16x2.f32 %0, %1, %2;" : "=r"(lo) : "f"(r1), "f"(r0));
    hi = h;
}

__device__ __forceinline__ void mma16816(float* d, const unsigned* a,
                                         unsigned b0, unsigned b1) {
    asm volatile(
        "mma.sync.aligned.m16n8k16.row.col.f32.bf16.bf16.f32 "
        "{%0,%1,%2,%3}, {%4,%5,%6,%7}, {%8,%9}, {%0,%1,%2,%3};"
        : "+f"(d[0]), "+f"(d[1]), "+f"(d[2]), "+f"(d[3])
        : "r"(a[0]), "r"(a[1]), "r"(a[2]), "r"(a[3]), "r"(b0), "r"(b1));
}

// ---------------------------------------------------------------------------
// Kernel 1: fused symmetrize + pack into mma B-fragment layout (bf16 hi/lo).
// ---------------------------------------------------------------------------
__device__ __forceinline__ float wsym_val(const float* __restrict__ w2,
                                          const float* __restrict__ b2,
                                          int k, int j, int w) {
    int p = j / 136, q = j % 136, u = 0;
    while (q >= 16 - u) { q -= 16 - u; u++; }
    int v = u + q;
    const float* src = (k < 64) ? (w2 + (size_t)k * 65536) : b2;
    float val = src[((p * 256 + u * 16 + v) << 7) + w];
    if (u != v) val += src[((p * 256 + v * 16 + u) << 7) + w];
    return val;
}

__global__ void bfrag_kernel(const float* __restrict__ w2,
                             const float* __restrict__ b2) {
    int idx = blockIdx.x * blockDim.x + threadIdx.x;
    const int total = NK * NJC * 16 * 32;
    if (idx >= total) return;
    int lane = idx & 31;
    int wt   = (idx >> 5) & 15;
    int rest = idx >> 9;
    int jc   = rest % NJC;
    int k    = rest / NJC;
    int w  = wt * 8 + (lane >> 2);
    int j0 = jc * 16 + (lane & 3) * 2;
    float v0 = wsym_val(w2, b2, k, j0,     w);
    float v1 = wsym_val(w2, b2, k, j0 + 1, w);
    float v2 = wsym_val(w2, b2, k, j0 + 8, w);
    float v3 = wsym_val(w2, b2, k, j0 + 9, w);
    uint4 o;
    split2(v0, v1, o.x, o.z);
    split2(v2, v3, o.y, o.w);
    g_bf[idx] = o;
}

// ---------------------------------------------------------------------------
// Kernel 2: fused prep — 16 rows/block (one m-tile, warp per row):
// h -> g_hT (transposed), c -> smem -> A-fragment quads g_cf.
// ---------------------------------------------------------------------------
__global__ __launch_bounds__(512) void prep_kernel(const float* __restrict__ x,
                                                   const float* __restrict__ lng,
                                                   const float* __restrict__ lnb,
                                                   const float* __restrict__ w1,
                                                   int N) {
    __shared__ float xs[16][64];
    __shared__ float lns[16][16];
    __shared__ float cs[16 * NJ];
    int tid = threadIdx.x;
    int warp = tid >> 5;
    int lane = tid & 31;
    int mt = blockIdx.x;
    int n = mt * 16 + warp;

    xs[warp][lane]      = x[(size_t)n * 64 + lane];
    xs[warp][lane + 32] = x[(size_t)n * 64 + 32 + lane];
    __syncwarp();

    float f = (lane < 16) ? xs[warp][lane] : 0.0f;
    float s = f;
    #pragma unroll
    for (int o = 16; o; o >>= 1) s += __shfl_xor_sync(0xffffffffu, s, o);
    float mu = s * (1.0f / 16.0f);
    float d = (lane < 16) ? (f - mu) : 0.0f;
    float ss = d * d;
    #pragma unroll
    for (int o = 16; o; o >>= 1) ss += __shfl_xor_sync(0xffffffffu, ss, o);
    float rstd = rsqrtf(ss * (1.0f / 16.0f) + LN_EPS);
    if (lane < 16) lns[warp][lane] = d * rstd * lng[lane] + lnb[lane];
    __syncwarp();

    #pragma unroll
    for (int t = 0; t < 2; t++) {
        int j = lane + 32 * t;
        float acc = 0.0f;
        #pragma unroll
        for (int i = 0; i < 16; i++) acc += lns[warp][i] * w1[i * 64 + j];
        g_hT[(size_t)j * MAXN + n] = silu_f(acc);
    }

    for (int t = lane; t < NJ; t += 32) {
        int p = t / 136, q = t % 136, u = 0;
        while (q >= 16 - u) { q -= 16 - u; u++; }
        int v = u + q;
        float val;
        if (p == 0) {
            val = PATH_COEFF * xs[warp][u] * xs[warp][v];
        } else {
            const float* a = &xs[warp][16 + u * 3];
            const float* b = &xs[warp][16 + v * 3];
            val = PATH_COEFF * CG110 * (a[0] * b[0] + a[1] * b[1] + a[2] * b[2]);
        }
        cs[warp * NJ + t] = val;
    }
    __syncthreads();

    // pack A-fragment quads for this m-tile
    for (int t = tid; t < NJC * 32; t += 512) {
        int l = t & 31;
        int jc = t >> 5;
        int ra = l >> 2;
        int j0 = jc * 16 + (l & 3) * 2;
        const float* c0 = cs + ra * NJ;
        const float* c8 = c0 + 8 * NJ;
        float4 f0, f1;
        f0.x = c0[j0];     f0.y = c0[j0 + 1]; f0.z = c8[j0];     f0.w = c8[j0 + 1];
        f1.x = c0[j0 + 8]; f1.y = c0[j0 + 9]; f1.z = c8[j0 + 8]; f1.w = c8[j0 + 9];
        size_t o = ((size_t)(mt * NJC + jc) * 32 + l) * 2;
        g_cf[o] = f0;
        g_cf[o + 1] = f1;
    }
}

// ---------------------------------------------------------------------------
// Kernel 3: HMMA contraction. Grid (N/128, KSPLIT=18), 256 threads (8 warps),
// 2 CTAs/SM. Warp = (mw: 32 rows, nh: 64 w-cols). acc[2 mtl][8 wt][4].
// ---------------------------------------------------------------------------
__global__ __launch_bounds__(256, 2) void tp_kernel(int N) {
    __shared__ float h_sm[4 * 128];
    int tid = threadIdx.x;
    int warp = tid >> 5;
    int lane = tid & 31;
    int mblk = blockIdx.x;
    int base = mblk * 128;
    int split = blockIdx.y;
    int k0 = (split * NK) / KSPLIT;
    int k1 = ((split + 1) * NK) / KSPLIT;
    int kc = k1 - k0;

    for (int s = tid; s < kc * 128; s += 256) {
        int k = k0 + (s >> 7);
        h_sm[s] = (k == 64) ? 1.0f : g_hT[(size_t)k * MAXN + base + (s & 127)];
    }
    __syncthreads();

    int mw = warp >> 1;
    int nh = warp & 1;
    int ra = lane >> 2;
    int qb = lane & 3;

    float acc[2][8][4];
    #pragma unroll
    for (int a = 0; a < 2; a++)
        #pragma unroll
        for (int b = 0; b < 8; b++)
            #pragma unroll
            for (int cdx = 0; cdx < 4; cdx++) acc[a][b][cdx] = 0.0f;

    for (int jc = 0; jc < NJC; jc++) {
        float4 cf[2][2];
        #pragma unroll
        for (int mtl = 0; mtl < 2; mtl++) {
            int mt = mblk * 8 + mw * 2 + mtl;
            size_t o = ((size_t)(mt * NJC + jc) * 32 + lane) * 2;
            cf[mtl][0] = g_cf[o];
            cf[mtl][1] = g_cf[o + 1];
        }
        for (int kk = 0; kk < kc; kk++) {
            unsigned ah[2][4], al[2][4];
            #pragma unroll
            for (int mtl = 0; mtl < 2; mtl++) {
                int r0 = mw * 32 + mtl * 16 + ra;
                float h0 = h_sm[kk * 128 + r0];
                float h1 = h_sm[kk * 128 + r0 + 8];
                split2(h0 * cf[mtl][0].x, h0 * cf[mtl][0].y, ah[mtl][0], al[mtl][0]);
                split2(h1 * cf[mtl][0].z, h1 * cf[mtl][0].w, ah[mtl][1], al[mtl][1]);
                split2(h0 * cf[mtl][1].x, h0 * cf[mtl][1].y, ah[mtl][2], al[mtl][2]);
                split2(h1 * cf[mtl][1].z, h1 * cf[mtl][1].w, ah[mtl][3], al[mtl][3]);
            }
            const uint4* bp = g_bf + (((size_t)(k0 + kk) * NJC + jc) * 16 + nh * 8) * 32 + lane;
            #pragma unroll
            for (int wt = 0; wt < 8; wt++) {
                uint4 bb = bp[(size_t)wt * 32];
                mma16816(acc[0][wt], ah[0], bb.x, bb.y);   // Ah*Bh
                mma16816(acc[1][wt], ah[1], bb.x, bb.y);
                mma16816(acc[0][wt], ah[0], bb.z, bb.w);   // Ah*Bl
                mma16816(acc[1][wt], ah[1], bb.z, bb.w);
                mma16816(acc[0][wt], al[0], bb.x, bb.y);   // Al*Bh
                mma16816(acc[1][wt], al[1], bb.x, bb.y);
            }
        }
    }

    // D layout: d0,d1 = (row ra, col 2qb,2qb+1); d2,d3 = row ra+8.
    #pragma unroll
    for (int mtl = 0; mtl < 2; mtl++) {
        int r0 = base + mw * 32 + mtl * 16 + ra;
        #pragma unroll
        for (int wt = 0; wt < 8; wt++) {
            int col = nh * 64 + wt * 8 + 2 * qb;
            float2* p0 = reinterpret_cast<float2*>(
                g_tp + ((size_t)split * N + r0) * 128 + col);
            float2* p1 = reinterpret_cast<float2*>(
                g_tp + ((size_t)split * N + r0 + 8) * 128 + col);
            *p0 = make_float2(acc[mtl][wt][0], acc[mtl][wt][1]);
            *p1 = make_float2(acc[mtl][wt][2], acc[mtl][wt][3]);
        }
    }
}

// ---------------------------------------------------------------------------
// Kernel 4: epilogue — sum 18 splits, LN(128), silu(@om_w1), @om_w2 + b.
// 16 rows per 256-thread block.
// ---------------------------------------------------------------------------
__global__ __launch_bounds__(256) void out_kernel(const float* __restrict__ lng,
                                                  const float* __restrict__ lnb,
                                                  const float* __restrict__ w1,
                                                  const float* __restrict__ w2,
                                                  const float* __restrict__ bias2,
                                                  float* __restrict__ out, int N) {
    __shared__ float ln_sm[16][128];
    __shared__ float part_sm[16][128];
    int tid = threadIdx.x, lane = tid & 31, warp = tid >> 5;
    int rowbase = blockIdx.x * 16;

    #pragma unroll
    for (int rr = 0; rr < 2; rr++) {
        int r = warp * 2 + rr;
        int g = rowbase + r;
        float v[4];
        #pragma unroll
        for (int t = 0; t < 4; t++) {
            int i = lane + 32 * t;
            float s = 0.0f;
            #pragma unroll
            for (int sp = 0; sp < KSPLIT; sp++)
                s += g_tp[((size_t)sp * N + g) * 128 + i];
            v[t] = s;
        }
        float s = v[0] + v[1] + v[2] + v[3];
        #pragma unroll
        for (int o = 16; o; o >>= 1) s += __shfl_xor_sync(0xffffffffu, s, o);
        float mu = s * (1.0f / 128.0f);
        float ss = 0.0f;
        #pragma unroll
        for (int t = 0; t < 4; t++) { float d = v[t] - mu; ss += d * d; }
        #pragma unroll
        for (int o = 16; o; o >>= 1) ss += __shfl_xor_sync(0xffffffffu, ss, o);
        float rstd = rsqrtf(ss * (1.0f / 128.0f) + LN_EPS);
        #pragma unroll
        for (int t = 0; t < 4; t++) {
            int i = lane + 32 * t;
            ln_sm[r][i] = (v[t] - mu) * rstd * lng[i] + lnb[i];
        }
    }
    __syncthreads();

    int q = tid & 127, hf = tid >> 7;
    float y[8][4];
    #pragma unroll
    for (int r = 0; r < 8; r++)
        #pragma unroll
        for (int cdx = 0; cdx < 4; cdx++) y[r][cdx] = 0.0f;

    const float4* w1v = reinterpret_cast<const float4*>(w1);
    #pragma unroll 4
    for (int i = 0; i < 128; i++) {
        float4 wv = w1v[i * 128 + q];
        #pragma unroll
        for (int r = 0; r < 8; r++) {
            float l = ln_sm[hf * 8 + r][i];
            y[r][0] += l * wv.x;
            y[r][1] += l * wv.y;
            y[r][2] += l * wv.z;
            y[r][3] += l * wv.w;
        }
    }
    float4 w2v = reinterpret_cast<const float4*>(w2)[q];
    #pragma unroll
    for (int r = 0; r < 8; r++) {
        part_sm[hf * 8 + r][q] =
            silu_f(y[r][0]) * w2v.x + silu_f(y[r][1]) * w2v.y +
            silu_f(y[r][2]) * w2v.z + silu_f(y[r][3]) * w2v.w;
    }
    __syncthreads();

    #pragma unroll
    for (int rr = 0; rr < 2; rr++) {
        int r = warp * 2 + rr;
        float s = part_sm[r][lane] + part_sm[r][lane + 32] +
                  part_sm[r][lane + 64] + part_sm[r][lane + 96];
        #pragma unroll
        for (int o = 16; o; o >>= 1) s += __shfl_xor_sync(0xffffffffu, s, o);
        if (lane == 0) out[rowbase + r] = s + bias2[0];
    }
}

// ---------------------------------------------------------------------------
extern "C" void kernel_launch(void* const* d_in, const int* in_sizes, int n_in,
                              void* d_out, int out_size) {
    const float* x        = (const float*)d_in[0];
    const float* we_ln_g  = (const float*)d_in[1];
    const float* we_ln_b  = (const float*)d_in[2];
    const float* we_w1    = (const float*)d_in[3];
    const float* we_w2    = (const float*)d_in[4];
    const float* we_b2    = (const float*)d_in[5];
    const float* om_ln_g  = (const float*)d_in[6];
    const float* om_ln_b  = (const float*)d_in[7];
    const float* om_w1    = (const float*)d_in[8];
    const float* om_w2    = (const float*)d_in[9];
    const float* om_b2    = (const float*)d_in[10];

    int N = in_sizes[0] / 64;
    if (N > MAXN) N = MAXN;

    const int totalF = NK * NJC * 16 * 32;

    bfrag_kernel<<<(totalF + 255) / 256, 256>>>(we_w2, we_b2);
    prep_kernel<<<N / 16, 512>>>(x, we_ln_g, we_ln_b, we_w1, N);
    tp_kernel<<<dim3(N / 128, KSPLIT), 256>>>(N);
    out_kernel<<<N / 16, 256>>>(om_ln_g, om_ln_b, om_w1, om_w2, om_b2,
                                (float*)d_out, N);
}

// round 9
// speedup vs baseline: 1.2365x; 1.0036x over previous
#include <cuda_runtime.h>
#include <cuda_bf16.h>

// ---------------------------------------------------------------------------
// WeightedTP via warp-level mma.sync (HMMA):
//   tp = A[2048 x 65*272] @ Wsym[65*272 x 128],  A[n,(k,j)] = h[n,k]*c[n,j]
// bf16 hi/lo 3-term split (AhBh + AhBl + AlBh), fp32 accumulate.
// R9: tp stages B fragments through double-buffered smem (1 cooperative load
//     per chunk, LDS broadcast to all mw warps, LDG prefetch 1 chunk ahead);
//     bfrag smem-tiled (coalesced); out_kernel back to R6 shape (8 rows/256).
// ---------------------------------------------------------------------------

#define MAXN 2048
#define NK 65            // 64 hidden + bias row (h=1)
#define NJ 272           // 17 chunks of 16
#define NJC 17
#define KSPLIT 18

#define PATH_COEFF 0.04419417382415922f
#define CG110      0.57735026918962576f
#define LN_EPS     1e-5f

__device__ float g_hT[64 * MAXN];                    // [k][n]
__device__ uint4 g_bf[(size_t)NK * NJC * 16 * 32];   // B frags [k][jc][wt][lane]
__device__ float4 g_cf[(size_t)(MAXN/16) * NJC * 32 * 2]; // c frags [mt][jc][lane][2]
__device__ float g_tp[(size_t)KSPLIT * MAXN * 128];

__device__ __forceinline__ float silu_f(float v) { return v / (1.0f + __expf(-v)); }

// split fp32 pair into bf16x2 hi + bf16x2 lo (a0 -> low half)
__device__ __forceinline__ void split2(float a0, float a1, unsigned& hi, unsigned& lo) {
    unsigned h;
    asm("cvt.rn.bf16x2.f32 %0, %1, %2;" : "=r"(h) : "f"(a1), "f"(a0));
    float h0 = __uint_as_float(h << 16);
    float h1 = __uint_as_float(h & 0xFFFF0000u);
    float r0 = a0 - h0, r1 = a1 - h1;
    asm("cvt.rn.bf16x2.f32 %0, %1, %2;" : "=r"(lo) : "f"(r1), "f"(r0));
    hi = h;
}

__device__ __forceinline__ void mma16816(float* d, const unsigned* a,
                                         unsigned b0, unsigned b1) {
    asm volatile(
        "mma.sync.aligned.m16n8k16.row.col.f32.bf16.bf16.f32 "
        "{%0,%1,%2,%3}, {%4,%5,%6,%7}, {%8,%9}, {%0,%1,%2,%3};"
        : "+f"(d[0]), "+f"(d[1]), "+f"(d[2]), "+f"(d[3])
        : "r"(a[0]), "r"(a[1]), "r"(a[2]), "r"(a[3]), "r"(b0), "r"(b1));
}

// ---------------------------------------------------------------------------
// Kernel 1: symmetrize + pack B fragments, smem-tiled. Block per (k, jc).
// ---------------------------------------------------------------------------
__global__ __launch_bounds__(256) void bfrag_kernel(const float* __restrict__ w2,
                                                    const float* __restrict__ b2) {
    __shared__ float sym[16][129];
    int bid = blockIdx.x;
    int k  = bid / NJC;
    int jc = bid % NJC;
    int tid = threadIdx.x;
    const float* src = (k < 64) ? (w2 + (size_t)k * 65536) : b2;

    #pragma unroll
    for (int i = 0; i < 8; i++) {
        int e  = tid + 256 * i;
        int pj = e >> 7;
        int w  = e & 127;
        int j = jc * 16 + pj;
        int p = j / 136, q = j % 136, u = 0;
        while (q >= 16 - u) { q -= 16 - u; u++; }
        int v = u + q;
        float val = src[((p * 256 + u * 16 + v) << 7) + w];
        if (u != v) val += src[((p * 256 + v * 16 + u) << 7) + w];
        sym[pj][w] = val;
    }
    __syncthreads();

    #pragma unroll
    for (int i = 0; i < 2; i++) {
        int s = tid + 256 * i;
        int wt = s >> 5;
        int lane = s & 31;
        int w = wt * 8 + (lane >> 2);
        int jl0 = (lane & 3) * 2;
        float v0 = sym[jl0][w],     v1 = sym[jl0 + 1][w];
        float v2 = sym[jl0 + 8][w], v3 = sym[jl0 + 9][w];
        uint4 o;
        split2(v0, v1, o.x, o.z);
        split2(v2, v3, o.y, o.w);
        g_bf[((size_t)(k * NJC + jc) * 16 + wt) * 32 + lane] = o;
    }
}

// ---------------------------------------------------------------------------
// Kernel 2: fused prep — 16 rows/block (warp per row):
// h -> g_hT (transposed), c -> smem -> A-fragment quads g_cf.
// ---------------------------------------------------------------------------
__global__ __launch_bounds__(512) void prep_kernel(const float* __restrict__ x,
                                                   const float* __restrict__ lng,
                                                   const float* __restrict__ lnb,
                                                   const float* __restrict__ w1,
                                                   int N) {
    __shared__ float xs[16][64];
    __shared__ float lns[16][16];
    __shared__ float cs[16 * NJ];
    int tid = threadIdx.x;
    int warp = tid >> 5;
    int lane = tid & 31;
    int mt = blockIdx.x;
    int n = mt * 16 + warp;

    xs[warp][lane]      = x[(size_t)n * 64 + lane];
    xs[warp][lane + 32] = x[(size_t)n * 64 + 32 + lane];
    __syncwarp();

    float f = (lane < 16) ? xs[warp][lane] : 0.0f;
    float s = f;
    #pragma unroll
    for (int o = 16; o; o >>= 1) s += __shfl_xor_sync(0xffffffffu, s, o);
    float mu = s * (1.0f / 16.0f);
    float d = (lane < 16) ? (f - mu) : 0.0f;
    float ss = d * d;
    #pragma unroll
    for (int o = 16; o; o >>= 1) ss += __shfl_xor_sync(0xffffffffu, ss, o);
    float rstd = rsqrtf(ss * (1.0f / 16.0f) + LN_EPS);
    if (lane < 16) lns[warp][lane] = d * rstd * lng[lane] + lnb[lane];
    __syncwarp();

    #pragma unroll
    for (int t = 0; t < 2; t++) {
        int j = lane + 32 * t;
        float acc = 0.0f;
        #pragma unroll
        for (int i = 0; i < 16; i++) acc += lns[warp][i] * w1[i * 64 + j];
        g_hT[(size_t)j * MAXN + n] = silu_f(acc);
    }

    for (int t = lane; t < NJ; t += 32) {
        int p = t / 136, q = t % 136, u = 0;
        while (q >= 16 - u) { q -= 16 - u; u++; }
        int v = u + q;
        float val;
        if (p == 0) {
            val = PATH_COEFF * xs[warp][u] * xs[warp][v];
        } else {
            const float* a = &xs[warp][16 + u * 3];
            const float* b = &xs[warp][16 + v * 3];
            val = PATH_COEFF * CG110 * (a[0] * b[0] + a[1] * b[1] + a[2] * b[2]);
        }
        cs[warp * NJ + t] = val;
    }
    __syncthreads();

    for (int t = tid; t < NJC * 32; t += 512) {
        int l = t & 31;
        int jc = t >> 5;
        int ra = l >> 2;
        int j0 = jc * 16 + (l & 3) * 2;
        const float* c0 = cs + ra * NJ;
        const float* c8 = c0 + 8 * NJ;
        float4 f0, f1;
        f0.x = c0[j0];     f0.y = c0[j0 + 1]; f0.z = c8[j0];     f0.w = c8[j0 + 1];
        f1.x = c0[j0 + 8]; f1.y = c0[j0 + 9]; f1.z = c8[j0 + 8]; f1.w = c8[j0 + 9];
        size_t o = ((size_t)(mt * NJC + jc) * 32 + l) * 2;
        g_cf[o] = f0;
        g_cf[o + 1] = f1;
    }
}

// ---------------------------------------------------------------------------
// Kernel 3: HMMA contraction. Grid (N/128, 18), 256 threads (8 warps),
// 2 CTA/SM. B fragments staged via double-buffered smem with LDG prefetch.
// Warp = (mw: 32 rows, nh: 64 w-cols). acc[2 mtl][8 wt][4].
// ---------------------------------------------------------------------------
__global__ __launch_bounds__(256, 2) void tp_kernel(int N) {
    __shared__ float h_sm[4 * 128];
    __shared__ uint4 sbuf[2][512];           // [buf][(nh*8+wt)*32+lane]
    int tid = threadIdx.x;
    int warp = tid >> 5;
    int lane = tid & 31;
    int mblk = blockIdx.x;
    int base = mblk * 128;
    int split = blockIdx.y;
    int k0 = (split * NK) / KSPLIT;
    int k1 = ((split + 1) * NK) / KSPLIT;
    int kc = k1 - k0;

    for (int s = tid; s < kc * 128; s += 256) {
        int k = k0 + (s >> 7);
        h_sm[s] = (k == 64) ? 1.0f : g_hT[(size_t)k * MAXN + base + (s & 127)];
    }
    // stage chunk 0 (jc=0, kk=0)
    {
        size_t off = (size_t)(k0 * NJC) * 512;
        sbuf[0][tid]       = g_bf[off + tid];
        sbuf[0][tid + 256] = g_bf[off + tid + 256];
    }
    __syncthreads();

    int mw = warp >> 1;
    int nh = warp & 1;
    int ra = lane >> 2;
    int qb = lane & 3;

    float acc[2][8][4];
    #pragma unroll
    for (int a = 0; a < 2; a++)
        #pragma unroll
        for (int b = 0; b < 8; b++)
            #pragma unroll
            for (int cdx = 0; cdx < 4; cdx++) acc[a][b][cdx] = 0.0f;

    const int T = NJC * kc;
    int t = 0;
    for (int jc = 0; jc < NJC; jc++) {
        float4 cf[2][2];
        #pragma unroll
        for (int mtl = 0; mtl < 2; mtl++) {
            int mt = mblk * 8 + mw * 2 + mtl;
            size_t o = ((size_t)(mt * NJC + jc) * 32 + lane) * 2;
            cf[mtl][0] = g_cf[o];
            cf[mtl][1] = g_cf[o + 1];
        }
        for (int kk = 0; kk < kc; kk++, t++) {
            int cur = t & 1, nxt = cur ^ 1;
            bool hn = (t + 1 < T);
            uint4 r0, r1;
            if (hn) {
                int kn = kk + 1, jn = jc;
                if (kn == kc) { kn = 0; jn = jc + 1; }
                size_t off = (size_t)((k0 + kn) * NJC + jn) * 512;
                r0 = g_bf[off + tid];
                r1 = g_bf[off + tid + 256];
            }
            // A fragments
            unsigned ah[2][4], al[2][4];
            #pragma unroll
            for (int mtl = 0; mtl < 2; mtl++) {
                int r0i = mw * 32 + mtl * 16 + ra;
                float h0 = h_sm[kk * 128 + r0i];
                float h1 = h_sm[kk * 128 + r0i + 8];
                split2(h0 * cf[mtl][0].x, h0 * cf[mtl][0].y, ah[mtl][0], al[mtl][0]);
                split2(h1 * cf[mtl][0].z, h1 * cf[mtl][0].w, ah[mtl][1], al[mtl][1]);
                split2(h0 * cf[mtl][1].x, h0 * cf[mtl][1].y, ah[mtl][2], al[mtl][2]);
                split2(h1 * cf[mtl][1].z, h1 * cf[mtl][1].w, ah[mtl][3], al[mtl][3]);
            }
            const uint4* bl = &sbuf[cur][nh * 256 + lane];
            #pragma unroll
            for (int wt = 0; wt < 8; wt++) {
                uint4 bb = bl[wt * 32];
                mma16816(acc[0][wt], ah[0], bb.x, bb.y);   // Ah*Bh
                mma16816(acc[1][wt], ah[1], bb.x, bb.y);
                mma16816(acc[0][wt], ah[0], bb.z, bb.w);   // Ah*Bl
                mma16816(acc[1][wt], ah[1], bb.z, bb.w);
                mma16816(acc[0][wt], al[0], bb.x, bb.y);   // Al*Bh
                mma16816(acc[1][wt], al[1], bb.x, bb.y);
            }
            if (hn) {
                sbuf[nxt][tid]       = r0;
                sbuf[nxt][tid + 256] = r1;
            }
            __syncthreads();
        }
    }

    // D layout: d0,d1 = (row ra, col 2qb,2qb+1); d2,d3 = row ra+8.
    #pragma unroll
    for (int mtl = 0; mtl < 2; mtl++) {
        int r0 = base + mw * 32 + mtl * 16 + ra;
        #pragma unroll
        for (int wt = 0; wt < 8; wt++) {
            int col = nh * 64 + wt * 8 + 2 * qb;
            float2* p0 = reinterpret_cast<float2*>(
                g_tp + ((size_t)split * N + r0) * 128 + col);
            float2* p1 = reinterpret_cast<float2*>(
                g_tp + ((size_t)split * N + r0 + 8) * 128 + col);
            *p0 = make_float2(acc[mtl][wt][0], acc[mtl][wt][1]);
            *p1 = make_float2(acc[mtl][wt][2], acc[mtl][wt][3]);
        }
    }
}

// ---------------------------------------------------------------------------
// Kernel 4: epilogue — sum 18 splits, LN(128), silu(@om_w1), @om_w2 + b.
// 8 rows per 256-thread block (grid N/8), i-dim split 2-way.
// ---------------------------------------------------------------------------
__global__ __launch_bounds__(256) void out_kernel(const float* __restrict__ lng,
                                                  const float* __restrict__ lnb,
                                                  const float* __restrict__ w1,
                                                  const float* __restrict__ w2,
                                                  const float* __restrict__ bias2,
                                                  float* __restrict__ out, int N) {
    __shared__ float ln_sm[8][128];
    __shared__ float y_sm[8][512];
    __shared__ float part_sm[8][128];
    int tid = threadIdx.x, lane = tid & 31, warp = tid >> 5;
    int rowbase = blockIdx.x * 8;

    // Phase A: one row per warp — sum splits + LayerNorm
    {
        int g = rowbase + warp;
        float v[4];
        #pragma unroll
        for (int t = 0; t < 4; t++) {
            int i = lane + 32 * t;
            float s = 0.0f;
            #pragma unroll
            for (int sp = 0; sp < KSPLIT; sp++)
                s += g_tp[((size_t)sp * N + g) * 128 + i];
            v[t] = s;
        }
        float s = v[0] + v[1] + v[2] + v[3];
        #pragma unroll
        for (int o = 16; o; o >>= 1) s += __shfl_xor_sync(0xffffffffu, s, o);
        float mu = s * (1.0f / 128.0f);
        float ss = 0.0f;
        #pragma unroll
        for (int t = 0; t < 4; t++) { float d = v[t] - mu; ss += d * d; }
        #pragma unroll
        for (int o = 16; o; o >>= 1) ss += __shfl_xor_sync(0xffffffffu, ss, o);
        float rstd = rsqrtf(ss * (1.0f / 128.0f) + LN_EPS);
        #pragma unroll
        for (int t = 0; t < 4; t++) {
            int i = lane + 32 * t;
            ln_sm[warp][i] = (v[t] - mu) * rstd * lng[i] + lnb[i];
        }
    }
    __syncthreads();

    // Phase B: y[r][q4] += ln[r][i] * w1[i][q4], i split across 2 halves
    int q = tid & 127, hf = tid >> 7;
    float y[8][4];
    #pragma unroll
    for (int r = 0; r < 8; r++)
        #pragma unroll
        for (int cdx = 0; cdx < 4; cdx++) y[r][cdx] = 0.0f;

    const float4* w1v = reinterpret_cast<const float4*>(w1);
    #pragma unroll 8
    for (int ii = 0; ii < 64; ii++) {
        int i = hf * 64 + ii;
        float4 wv = w1v[i * 128 + q];
        #pragma unroll
        for (int r = 0; r < 8; r++) {
            float l = ln_sm[r][i];
            y[r][0] += l * wv.x;
            y[r][1] += l * wv.y;
            y[r][2] += l * wv.z;
            y[r][3] += l * wv.w;
        }
    }
    if (hf == 1) {
        #pragma unroll
        for (int r = 0; r < 8; r++) {
            y_sm[r][q * 4]     = y[r][0];
            y_sm[r][q * 4 + 1] = y[r][1];
            y_sm[r][q * 4 + 2] = y[r][2];
            y_sm[r][q * 4 + 3] = y[r][3];
        }
    }
    __syncthreads();

    if (hf == 0) {
        float4 w2v = reinterpret_cast<const float4*>(w2)[q];
        #pragma unroll
        for (int r = 0; r < 8; r++) {
            float a0 = y[r][0] + y_sm[r][q * 4];
            float a1 = y[r][1] + y_sm[r][q * 4 + 1];
            float a2 = y[r][2] + y_sm[r][q * 4 + 2];
            float a3 = y[r][3] + y_sm[r][q * 4 + 3];
            part_sm[r][q] = silu_f(a0) * w2v.x + silu_f(a1) * w2v.y +
                            silu_f(a2) * w2v.z + silu_f(a3) * w2v.w;
        }
    }
    __syncthreads();

    {
        float s = part_sm[warp][lane] + part_sm[warp][lane + 32] +
                  part_sm[warp][lane + 64] + part_sm[warp][lane + 96];
        #pragma unroll
        for (int o = 16; o; o >>= 1) s += __shfl_xor_sync(0xffffffffu, s, o);
        if (lane == 0) out[rowbase + warp] = s + bias2[0];
    }
}

// ---------------------------------------------------------------------------
extern "C" void kernel_launch(void* const* d_in, const int* in_sizes, int n_in,
                              void* d_out, int out_size) {
    const float* x        = (const float*)d_in[0];
    const float* we_ln_g  = (const float*)d_in[1];
    const float* we_ln_b  = (const float*)d_in[2];
    const float* we_w1    = (const float*)d_in[3];
    const float* we_w2    = (const float*)d_in[4];
    const float* we_b2    = (const float*)d_in[5];
    const float* om_ln_g  = (const float*)d_in[6];
    const float* om_ln_b  = (const float*)d_in[7];
    const float* om_w1    = (const float*)d_in[8];
    const float* om_w2    = (const float*)d_in[9];
    const float* om_b2    = (const float*)d_in[10];

    int N = in_sizes[0] / 64;
    if (N > MAXN) N = MAXN;

    bfrag_kernel<<<NK * NJC, 256>>>(we_w2, we_b2);
    prep_kernel<<<N / 16, 512>>>(x, we_ln_g, we_ln_b, we_w1, N);
    tp_kernel<<<dim3(N / 128, KSPLIT), 256>>>(N);
    out_kernel<<<N / 8, 256>>>(om_ln_g, om_ln_b, om_w1, om_w2, om_b2,
                               (float*)d_out, N);
}

// round 10
// speedup vs baseline: 1.4429x; 1.1669x over previous
#include <cuda_runtime.h>
#include <cuda_fp16.h>

// ---------------------------------------------------------------------------
// WeightedTP via warp-level mma.sync (HMMA, fp16 2-term split):
//   tp = A[2048 x 65*272] @ Wsym[65*272 x 128],  A[n,(k,j)] = h[n,k]*c[n,j]
// A split into fp16 hi/lo (exact to 2^-22); B single fp16 plane.
// D = Ah*Bh + Al*Bh  (dropped A*Bl ~ 2^-12 -> rel_err ~1e-4 << 1e-3).
// R10: 33% fewer HMMA + halved B traffic vs bf16 3-term.
// ---------------------------------------------------------------------------

#define MAXN 2048
#define NK 65            // 64 hidden + bias row (h=1)
#define NJ 272           // 17 chunks of 16
#define NJC 17
#define KSPLIT 18

#define PATH_COEFF 0.04419417382415922f
#define CG110      0.57735026918962576f
#define LN_EPS     1e-5f

__device__ float g_hT[64 * MAXN];                    // [k][n]
__device__ uint2 g_bf[(size_t)NK * NJC * 16 * 32];   // B frags (fp16) [k][jc][wt][lane]
__device__ float4 g_cf[(size_t)(MAXN/16) * NJC * 32 * 2]; // c frags [mt][jc][lane][2]
__device__ float g_tp[(size_t)KSPLIT * MAXN * 128];

__device__ __forceinline__ float silu_f(float v) { return v / (1.0f + __expf(-v)); }

// split fp32 pair into f16x2 hi + f16x2 lo (a0 -> low half)
__device__ __forceinline__ void split2h(float a0, float a1, unsigned& hi, unsigned& lo) {
    __half2 h = __floats2half2_rn(a0, a1);
    float2 hf = __half22float2(h);
    __half2 l = __floats2half2_rn(a0 - hf.x, a1 - hf.y);
    hi = *reinterpret_cast<unsigned*>(&h);
    lo = *reinterpret_cast<unsigned*>(&l);
}

__device__ __forceinline__ void mma16816(float* d, const unsigned* a,
                                         unsigned b0, unsigned b1) {
    asm volatile(
        "mma.sync.aligned.m16n8k16.row.col.f32.f16.f16.f32 "
        "{%0,%1,%2,%3}, {%4,%5,%6,%7}, {%8,%9}, {%0,%1,%2,%3};"
        : "+f"(d[0]), "+f"(d[1]), "+f"(d[2]), "+f"(d[3])
        : "r"(a[0]), "r"(a[1]), "r"(a[2]), "r"(a[3]), "r"(b0), "r"(b1));
}

// ---------------------------------------------------------------------------
// Kernel 1: symmetrize + pack B fragments (single fp16 plane), smem-tiled.
// Block per (k, jc).
// ---------------------------------------------------------------------------
__global__ __launch_bounds__(256) void bfrag_kernel(const float* __restrict__ w2,
                                                    const float* __restrict__ b2) {
    __shared__ float sym[16][129];
    int bid = blockIdx.x;
    int k  = bid / NJC;
    int jc = bid % NJC;
    int tid = threadIdx.x;
    const float* src = (k < 64) ? (w2 + (size_t)k * 65536) : b2;

    #pragma unroll
    for (int i = 0; i < 8; i++) {
        int e  = tid + 256 * i;
        int pj = e >> 7;
        int w  = e & 127;
        int j = jc * 16 + pj;
        int p = j / 136, q = j % 136, u = 0;
        while (q >= 16 - u) { q -= 16 - u; u++; }
        int v = u + q;
        float val = src[((p * 256 + u * 16 + v) << 7) + w];
        if (u != v) val += src[((p * 256 + v * 16 + u) << 7) + w];
        sym[pj][w] = val;
    }
    __syncthreads();

    #pragma unroll
    for (int i = 0; i < 2; i++) {
        int s = tid + 256 * i;
        int wt = s >> 5;
        int lane = s & 31;
        int w = wt * 8 + (lane >> 2);
        int jl0 = (lane & 3) * 2;
        __half2 h0 = __floats2half2_rn(sym[jl0][w],     sym[jl0 + 1][w]);
        __half2 h1 = __floats2half2_rn(sym[jl0 + 8][w], sym[jl0 + 9][w]);
        uint2 o;
        o.x = *reinterpret_cast<unsigned*>(&h0);
        o.y = *reinterpret_cast<unsigned*>(&h1);
        g_bf[((size_t)(k * NJC + jc) * 16 + wt) * 32 + lane] = o;
    }
}

// ---------------------------------------------------------------------------
// Kernel 2: fused prep — 16 rows/block (warp per row):
// h -> g_hT (transposed), c -> smem -> A-fragment quads g_cf.
// ---------------------------------------------------------------------------
__global__ __launch_bounds__(512) void prep_kernel(const float* __restrict__ x,
                                                   const float* __restrict__ lng,
                                                   const float* __restrict__ lnb,
                                                   const float* __restrict__ w1,
                                                   int N) {
    __shared__ float xs[16][64];
    __shared__ float lns[16][16];
    __shared__ float cs[16 * NJ];
    int tid = threadIdx.x;
    int warp = tid >> 5;
    int lane = tid & 31;
    int mt = blockIdx.x;
    int n = mt * 16 + warp;

    xs[warp][lane]      = x[(size_t)n * 64 + lane];
    xs[warp][lane + 32] = x[(size_t)n * 64 + 32 + lane];
    __syncwarp();

    float f = (lane < 16) ? xs[warp][lane] : 0.0f;
    float s = f;
    #pragma unroll
    for (int o = 16; o; o >>= 1) s += __shfl_xor_sync(0xffffffffu, s, o);
    float mu = s * (1.0f / 16.0f);
    float d = (lane < 16) ? (f - mu) : 0.0f;
    float ss = d * d;
    #pragma unroll
    for (int o = 16; o; o >>= 1) ss += __shfl_xor_sync(0xffffffffu, ss, o);
    float rstd = rsqrtf(ss * (1.0f / 16.0f) + LN_EPS);
    if (lane < 16) lns[warp][lane] = d * rstd * lng[lane] + lnb[lane];
    __syncwarp();

    #pragma unroll
    for (int t = 0; t < 2; t++) {
        int j = lane + 32 * t;
        float acc = 0.0f;
        #pragma unroll
        for (int i = 0; i < 16; i++) acc += lns[warp][i] * w1[i * 64 + j];
        g_hT[(size_t)j * MAXN + n] = silu_f(acc);
    }

    for (int t = lane; t < NJ; t += 32) {
        int p = t / 136, q = t % 136, u = 0;
        while (q >= 16 - u) { q -= 16 - u; u++; }
        int v = u + q;
        float val;
        if (p == 0) {
            val = PATH_COEFF * xs[warp][u] * xs[warp][v];
        } else {
            const float* a = &xs[warp][16 + u * 3];
            const float* b = &xs[warp][16 + v * 3];
            val = PATH_COEFF * CG110 * (a[0] * b[0] + a[1] * b[1] + a[2] * b[2]);
        }
        cs[warp * NJ + t] = val;
    }
    __syncthreads();

    for (int t = tid; t < NJC * 32; t += 512) {
        int l = t & 31;
        int jc = t >> 5;
        int ra = l >> 2;
        int j0 = jc * 16 + (l & 3) * 2;
        const float* c0 = cs + ra * NJ;
        const float* c8 = c0 + 8 * NJ;
        float4 f0, f1;
        f0.x = c0[j0];     f0.y = c0[j0 + 1]; f0.z = c8[j0];     f0.w = c8[j0 + 1];
        f1.x = c0[j0 + 8]; f1.y = c0[j0 + 9]; f1.z = c8[j0 + 8]; f1.w = c8[j0 + 9];
        size_t o = ((size_t)(mt * NJC + jc) * 32 + l) * 2;
        g_cf[o] = f0;
        g_cf[o + 1] = f1;
    }
}

// ---------------------------------------------------------------------------
// Kernel 3: HMMA contraction, fp16 2-term. Grid (N/128, 18), 256 threads,
// 2 CTA/SM. B staged via double-buffered smem (uint2) with LDG prefetch.
// Warp = (mw: 32 rows, nh: 64 w-cols). acc[2 mtl][8 wt][4].
// ---------------------------------------------------------------------------
__global__ __launch_bounds__(256, 2) void tp_kernel(int N) {
    __shared__ float h_sm[4 * 128];
    __shared__ uint2 sbuf[2][512];           // [buf][(nh*8+wt)*32+lane]
    int tid = threadIdx.x;
    int warp = tid >> 5;
    int lane = tid & 31;
    int mblk = blockIdx.x;
    int base = mblk * 128;
    int split = blockIdx.y;
    int k0 = (split * NK) / KSPLIT;
    int k1 = ((split + 1) * NK) / KSPLIT;
    int kc = k1 - k0;

    for (int s = tid; s < kc * 128; s += 256) {
        int k = k0 + (s >> 7);
        h_sm[s] = (k == 64) ? 1.0f : g_hT[(size_t)k * MAXN + base + (s & 127)];
    }
    {   // stage chunk 0 (jc=0, kk=0)
        size_t off = (size_t)(k0 * NJC) * 512;
        sbuf[0][tid]       = g_bf[off + tid];
        sbuf[0][tid + 256] = g_bf[off + tid + 256];
    }
    __syncthreads();

    int mw = warp >> 1;
    int nh = warp & 1;
    int ra = lane >> 2;
    int qb = lane & 3;

    float acc[2][8][4];
    #pragma unroll
    for (int a = 0; a < 2; a++)
        #pragma unroll
        for (int b = 0; b < 8; b++)
            #pragma unroll
            for (int cdx = 0; cdx < 4; cdx++) acc[a][b][cdx] = 0.0f;

    const int T = NJC * kc;
    int t = 0;
    for (int jc = 0; jc < NJC; jc++) {
        float4 cf[2][2];
        #pragma unroll
        for (int mtl = 0; mtl < 2; mtl++) {
            int mt = mblk * 8 + mw * 2 + mtl;
            size_t o = ((size_t)(mt * NJC + jc) * 32 + lane) * 2;
            cf[mtl][0] = g_cf[o];
            cf[mtl][1] = g_cf[o + 1];
        }
        for (int kk = 0; kk < kc; kk++, t++) {
            int cur = t & 1, nxt = cur ^ 1;
            bool hn = (t + 1 < T);
            uint2 r0, r1;
            if (hn) {
                int kn = kk + 1, jn = jc;
                if (kn == kc) { kn = 0; jn = jc + 1; }
                size_t off = (size_t)((k0 + kn) * NJC + jn) * 512;
                r0 = g_bf[off + tid];
                r1 = g_bf[off + tid + 256];
            }
            // A fragments: fp16 hi/lo split of h*c (exact in fp32 first)
            unsigned ah[2][4], al[2][4];
            #pragma unroll
            for (int mtl = 0; mtl < 2; mtl++) {
                int r0i = mw * 32 + mtl * 16 + ra;
                float h0 = h_sm[kk * 128 + r0i];
                float h1 = h_sm[kk * 128 + r0i + 8];
                split2h(h0 * cf[mtl][0].x, h0 * cf[mtl][0].y, ah[mtl][0], al[mtl][0]);
                split2h(h1 * cf[mtl][0].z, h1 * cf[mtl][0].w, ah[mtl][1], al[mtl][1]);
                split2h(h0 * cf[mtl][1].x, h0 * cf[mtl][1].y, ah[mtl][2], al[mtl][2]);
                split2h(h1 * cf[mtl][1].z, h1 * cf[mtl][1].w, ah[mtl][3], al[mtl][3]);
            }
            const uint2* bl = &sbuf[cur][nh * 256 + lane];
            #pragma unroll
            for (int wt = 0; wt < 8; wt++) {
                uint2 bb = bl[wt * 32];
                mma16816(acc[0][wt], ah[0], bb.x, bb.y);   // Ah*Bh
                mma16816(acc[1][wt], ah[1], bb.x, bb.y);
                mma16816(acc[0][wt], al[0], bb.x, bb.y);   // Al*Bh
                mma16816(acc[1][wt], al[1], bb.x, bb.y);
            }
            if (hn) {
                sbuf[nxt][tid]       = r0;
                sbuf[nxt][tid + 256] = r1;
            }
            __syncthreads();
        }
    }

    // D layout: d0,d1 = (row ra, col 2qb,2qb+1); d2,d3 = row ra+8.
    #pragma unroll
    for (int mtl = 0; mtl < 2; mtl++) {
        int r0 = base + mw * 32 + mtl * 16 + ra;
        #pragma unroll
        for (int wt = 0; wt < 8; wt++) {
            int col = nh * 64 + wt * 8 + 2 * qb;
            float2* p0 = reinterpret_cast<float2*>(
                g_tp + ((size_t)split * N + r0) * 128 + col);
            float2* p1 = reinterpret_cast<float2*>(
                g_tp + ((size_t)split * N + r0 + 8) * 128 + col);
            *p0 = make_float2(acc[mtl][wt][0], acc[mtl][wt][1]);
            *p1 = make_float2(acc[mtl][wt][2], acc[mtl][wt][3]);
        }
    }
}

// ---------------------------------------------------------------------------
// Kernel 4: epilogue — sum 18 splits, LN(128), silu(@om_w1), @om_w2 + b.
// 8 rows per 256-thread block, i-dim split 2-way.
// ---------------------------------------------------------------------------
__global__ __launch_bounds__(256) void out_kernel(const float* __restrict__ lng,
                                                  const float* __restrict__ lnb,
                                                  const float* __restrict__ w1,
                                                  const float* __restrict__ w2,
                                                  const float* __restrict__ bias2,
                                                  float* __restrict__ out, int N) {
    __shared__ float ln_sm[8][128];
    __shared__ float y_sm[8][512];
    __shared__ float part_sm[8][128];
    int tid = threadIdx.x, lane = tid & 31, warp = tid >> 5;
    int rowbase = blockIdx.x * 8;

    {
        int g = rowbase + warp;
        float v[4];
        #pragma unroll
        for (int t = 0; t < 4; t++) {
            int i = lane + 32 * t;
            float s = 0.0f;
            #pragma unroll
            for (int sp = 0; sp < KSPLIT; sp++)
                s += g_tp[((size_t)sp * N + g) * 128 + i];
            v[t] = s;
        }
        float s = v[0] + v[1] + v[2] + v[3];
        #pragma unroll
        for (int o = 16; o; o >>= 1) s += __shfl_xor_sync(0xffffffffu, s, o);
        float mu = s * (1.0f / 128.0f);
        float ss = 0.0f;
        #pragma unroll
        for (int t = 0; t < 4; t++) { float d = v[t] - mu; ss += d * d; }
        #pragma unroll
        for (int o = 16; o; o >>= 1) ss += __shfl_xor_sync(0xffffffffu, ss, o);
        float rstd = rsqrtf(ss * (1.0f / 128.0f) + LN_EPS);
        #pragma unroll
        for (int t = 0; t < 4; t++) {
            int i = lane + 32 * t;
            ln_sm[warp][i] = (v[t] - mu) * rstd * lng[i] + lnb[i];
        }
    }
    __syncthreads();

    int q = tid & 127, hf = tid >> 7;
    float y[8][4];
    #pragma unroll
    for (int r = 0; r < 8; r++)
        #pragma unroll
        for (int cdx = 0; cdx < 4; cdx++) y[r][cdx] = 0.0f;

    const float4* w1v = reinterpret_cast<const float4*>(w1);
    #pragma unroll 8
    for (int ii = 0; ii < 64; ii++) {
        int i = hf * 64 + ii;
        float4 wv = w1v[i * 128 + q];
        #pragma unroll
        for (int r = 0; r < 8; r++) {
            float l = ln_sm[r][i];
            y[r][0] += l * wv.x;
            y[r][1] += l * wv.y;
            y[r][2] += l * wv.z;
            y[r][3] += l * wv.w;
        }
    }
    if (hf == 1) {
        #pragma unroll
        for (int r = 0; r < 8; r++) {
            y_sm[r][q * 4]     = y[r][0];
            y_sm[r][q * 4 + 1] = y[r][1];
            y_sm[r][q * 4 + 2] = y[r][2];
            y_sm[r][q * 4 + 3] = y[r][3];
        }
    }
    __syncthreads();

    if (hf == 0) {
        float4 w2v = reinterpret_cast<const float4*>(w2)[q];
        #pragma unroll
        for (int r = 0; r < 8; r++) {
            float a0 = y[r][0] + y_sm[r][q * 4];
            float a1 = y[r][1] + y_sm[r][q * 4 + 1];
            float a2 = y[r][2] + y_sm[r][q * 4 + 2];
            float a3 = y[r][3] + y_sm[r][q * 4 + 3];
            part_sm[r][q] = silu_f(a0) * w2v.x + silu_f(a1) * w2v.y +
                            silu_f(a2) * w2v.z + silu_f(a3) * w2v.w;
        }
    }
    __syncthreads();

    {
        float s = part_sm[warp][lane] + part_sm[warp][lane + 32] +
                  part_sm[warp][lane + 64] + part_sm[warp][lane + 96];
        #pragma unroll
        for (int o = 16; o; o >>= 1) s += __shfl_xor_sync(0xffffffffu, s, o);
        if (lane == 0) out[rowbase + warp] = s + bias2[0];
    }
}

// ---------------------------------------------------------------------------
extern "C" void kernel_launch(void* const* d_in, const int* in_sizes, int n_in,
                              void* d_out, int out_size) {
    const float* x        = (const float*)d_in[0];
    const float* we_ln_g  = (const float*)d_in[1];
    const float* we_ln_b  = (const float*)d_in[2];
    const float* we_w1    = (const float*)d_in[3];
    const float* we_w2    = (const float*)d_in[4];
    const float* we_b2    = (const float*)d_in[5];
    const float* om_ln_g  = (const float*)d_in[6];
    const float* om_ln_b  = (const float*)d_in[7];
    const float* om_w1    = (const float*)d_in[8];
    const float* om_w2    = (const float*)d_in[9];
    const float* om_b2    = (const float*)d_in[10];

    int N = in_sizes[0] / 64;
    if (N > MAXN) N = MAXN;

    bfrag_kernel<<<NK * NJC, 256>>>(we_w2, we_b2);
    prep_kernel<<<N / 16, 512>>>(x, we_ln_g, we_ln_b, we_w1, N);
    tp_kernel<<<dim3(N / 128, KSPLIT), 256>>>(N);
    out_kernel<<<N / 8, 256>>>(om_ln_g, om_ln_b, om_w1, om_w2, om_b2,
                               (float*)d_out, N);
}

// round 11
// speedup vs baseline: 1.6802x; 1.1645x over previous
#include <cuda_runtime.h>
#include <cuda_fp16.h>

// ---------------------------------------------------------------------------
// WeightedTP via warp-level mma.sync (HMMA, fp16 2-term split):
//   tp = A[2048 x 65*272] @ Wsym[65*272 x 128],  A[n,(k,j)] = h[n,k]*c[n,j]
// A split into fp16 hi/lo (exact); B single fp16 plane.
// D = Ah*Bh + Al*Bh  (error = A*(B-fl16(B)) ~ 2e-4 rel, << 1e-3).
// R11: warp tile 16x128 (8 warps x 16 rows) -> A-gen halved per HMMA
//      (4 split2h + 8 FMUL per warp-iter for the same 32 HMMA).
// ---------------------------------------------------------------------------

#define MAXN 2048
#define NK 65            // 64 hidden + bias row (h=1)
#define NJ 272           // 17 chunks of 16
#define NJC 17
#define KSPLIT 18

#define PATH_COEFF 0.04419417382415922f
#define CG110      0.57735026918962576f
#define LN_EPS     1e-5f

__device__ float g_hT[64 * MAXN];                    // [k][n]
__device__ uint2 g_bf[(size_t)NK * NJC * 16 * 32];   // B frags (fp16) [k][jc][wt][lane]
__device__ float4 g_cf[(size_t)(MAXN/16) * NJC * 32 * 2]; // c frags [mt][jc][lane][2]
__device__ float g_tp[(size_t)KSPLIT * MAXN * 128];

__device__ __forceinline__ float silu_f(float v) { return v / (1.0f + __expf(-v)); }

// split fp32 pair into f16x2 hi + f16x2 lo (a0 -> low half)
__device__ __forceinline__ void split2h(float a0, float a1, unsigned& hi, unsigned& lo) {
    __half2 h = __floats2half2_rn(a0, a1);
    float2 hf = __half22float2(h);
    __half2 l = __floats2half2_rn(a0 - hf.x, a1 - hf.y);
    hi = *reinterpret_cast<unsigned*>(&h);
    lo = *reinterpret_cast<unsigned*>(&l);
}

__device__ __forceinline__ void mma16816(float* d, const unsigned* a,
                                         unsigned b0, unsigned b1) {
    asm volatile(
        "mma.sync.aligned.m16n8k16.row.col.f32.f16.f16.f32 "
        "{%0,%1,%2,%3}, {%4,%5,%6,%7}, {%8,%9}, {%0,%1,%2,%3};"
        : "+f"(d[0]), "+f"(d[1]), "+f"(d[2]), "+f"(d[3])
        : "r"(a[0]), "r"(a[1]), "r"(a[2]), "r"(a[3]), "r"(b0), "r"(b1));
}

// ---------------------------------------------------------------------------
// Kernel 1: symmetrize + pack B fragments (single fp16 plane), smem-tiled.
// Block per (k, jc).
// ---------------------------------------------------------------------------
__global__ __launch_bounds__(256) void bfrag_kernel(const float* __restrict__ w2,
                                                    const float* __restrict__ b2) {
    __shared__ float sym[16][129];
    int bid = blockIdx.x;
    int k  = bid / NJC;
    int jc = bid % NJC;
    int tid = threadIdx.x;
    const float* src = (k < 64) ? (w2 + (size_t)k * 65536) : b2;

    #pragma unroll
    for (int i = 0; i < 8; i++) {
        int e  = tid + 256 * i;
        int pj = e >> 7;
        int w  = e & 127;
        int j = jc * 16 + pj;
        int p = j / 136, q = j % 136, u = 0;
        while (q >= 16 - u) { q -= 16 - u; u++; }
        int v = u + q;
        float val = src[((p * 256 + u * 16 + v) << 7) + w];
        if (u != v) val += src[((p * 256 + v * 16 + u) << 7) + w];
        sym[pj][w] = val;
    }
    __syncthreads();

    #pragma unroll
    for (int i = 0; i < 2; i++) {
        int s = tid + 256 * i;
        int wt = s >> 5;
        int lane = s & 31;
        int w = wt * 8 + (lane >> 2);
        int jl0 = (lane & 3) * 2;
        __half2 h0 = __floats2half2_rn(sym[jl0][w],     sym[jl0 + 1][w]);
        __half2 h1 = __floats2half2_rn(sym[jl0 + 8][w], sym[jl0 + 9][w]);
        uint2 o;
        o.x = *reinterpret_cast<unsigned*>(&h0);
        o.y = *reinterpret_cast<unsigned*>(&h1);
        g_bf[((size_t)(k * NJC + jc) * 16 + wt) * 32 + lane] = o;
    }
}

// ---------------------------------------------------------------------------
// Kernel 2: fused prep — 16 rows/block (warp per row):
// h -> g_hT (transposed), c -> smem -> A-fragment quads g_cf.
// ---------------------------------------------------------------------------
__global__ __launch_bounds__(512) void prep_kernel(const float* __restrict__ x,
                                                   const float* __restrict__ lng,
                                                   const float* __restrict__ lnb,
                                                   const float* __restrict__ w1,
                                                   int N) {
    __shared__ float xs[16][64];
    __shared__ float lns[16][16];
    __shared__ float cs[16 * NJ];
    int tid = threadIdx.x;
    int warp = tid >> 5;
    int lane = tid & 31;
    int mt = blockIdx.x;
    int n = mt * 16 + warp;

    xs[warp][lane]      = x[(size_t)n * 64 + lane];
    xs[warp][lane + 32] = x[(size_t)n * 64 + 32 + lane];
    __syncwarp();

    float f = (lane < 16) ? xs[warp][lane] : 0.0f;
    float s = f;
    #pragma unroll
    for (int o = 16; o; o >>= 1) s += __shfl_xor_sync(0xffffffffu, s, o);
    float mu = s * (1.0f / 16.0f);
    float d = (lane < 16) ? (f - mu) : 0.0f;
    float ss = d * d;
    #pragma unroll
    for (int o = 16; o; o >>= 1) ss += __shfl_xor_sync(0xffffffffu, ss, o);
    float rstd = rsqrtf(ss * (1.0f / 16.0f) + LN_EPS);
    if (lane < 16) lns[warp][lane] = d * rstd * lng[lane] + lnb[lane];
    __syncwarp();

    #pragma unroll
    for (int t = 0; t < 2; t++) {
        int j = lane + 32 * t;
        float acc = 0.0f;
        #pragma unroll
        for (int i = 0; i < 16; i++) acc += lns[warp][i] * w1[i * 64 + j];
        g_hT[(size_t)j * MAXN + n] = silu_f(acc);
    }

    for (int t = lane; t < NJ; t += 32) {
        int p = t / 136, q = t % 136, u = 0;
        while (q >= 16 - u) { q -= 16 - u; u++; }
        int v = u + q;
        float val;
        if (p == 0) {
            val = PATH_COEFF * xs[warp][u] * xs[warp][v];
        } else {
            const float* a = &xs[warp][16 + u * 3];
            const float* b = &xs[warp][16 + v * 3];
            val = PATH_COEFF * CG110 * (a[0] * b[0] + a[1] * b[1] + a[2] * b[2]);
        }
        cs[warp * NJ + t] = val;
    }
    __syncthreads();

    for (int t = tid; t < NJC * 32; t += 512) {
        int l = t & 31;
        int jc = t >> 5;
        int ra = l >> 2;
        int j0 = jc * 16 + (l & 3) * 2;
        const float* c0 = cs + ra * NJ;
        const float* c8 = c0 + 8 * NJ;
        float4 f0, f1;
        f0.x = c0[j0];     f0.y = c0[j0 + 1]; f0.z = c8[j0];     f0.w = c8[j0 + 1];
        f1.x = c0[j0 + 8]; f1.y = c0[j0 + 9]; f1.z = c8[j0 + 8]; f1.w = c8[j0 + 9];
        size_t o = ((size_t)(mt * NJC + jc) * 32 + l) * 2;
        g_cf[o] = f0;
        g_cf[o + 1] = f1;
    }
}

// ---------------------------------------------------------------------------
// Kernel 3: HMMA contraction, fp16 2-term. Grid (N/128, 18), 256 threads,
// 2 CTA/SM. Warp tile 16 rows x 128 cols (warp = m-slice, no nh duplication).
// B staged via double-buffered smem (uint2) with LDG prefetch.
// ---------------------------------------------------------------------------
__global__ __launch_bounds__(256, 2) void tp_kernel(int N) {
    __shared__ float h_sm[4 * 128];
    __shared__ uint2 sbuf[2][512];           // [buf][wt*32+lane]
    int tid = threadIdx.x;
    int warp = tid >> 5;
    int lane = tid & 31;
    int mblk = blockIdx.x;
    int base = mblk * 128;
    int split = blockIdx.y;
    int k0 = (split * NK) / KSPLIT;
    int k1 = ((split + 1) * NK) / KSPLIT;
    int kc = k1 - k0;

    for (int s = tid; s < kc * 128; s += 256) {
        int k = k0 + (s >> 7);
        h_sm[s] = (k == 64) ? 1.0f : g_hT[(size_t)k * MAXN + base + (s & 127)];
    }
    {   // stage chunk 0 (jc=0, kk=0)
        size_t off = (size_t)(k0 * NJC) * 512;
        sbuf[0][tid]       = g_bf[off + tid];
        sbuf[0][tid + 256] = g_bf[off + tid + 256];
    }
    __syncthreads();

    int ra = lane >> 2;
    int qb = lane & 3;
    int mt = mblk * 8 + warp;      // 16-row tile owned by this warp
    int r0i = warp * 16 + ra;      // row within 128-row CTA tile

    float acc[16][4];
    #pragma unroll
    for (int b = 0; b < 16; b++)
        #pragma unroll
        for (int cdx = 0; cdx < 4; cdx++) acc[b][cdx] = 0.0f;

    const int T = NJC * kc;
    int t = 0;
    for (int jc = 0; jc < NJC; jc++) {
        size_t o = ((size_t)(mt * NJC + jc) * 32 + lane) * 2;
        float4 cf0 = g_cf[o];
        float4 cf1 = g_cf[o + 1];
        for (int kk = 0; kk < kc; kk++, t++) {
            int cur = t & 1, nxt = cur ^ 1;
            bool hn = (t + 1 < T);
            uint2 p0, p1;
            if (hn) {
                int kn = kk + 1, jn = jc;
                if (kn == kc) { kn = 0; jn = jc + 1; }
                size_t off = (size_t)((k0 + kn) * NJC + jn) * 512;
                p0 = g_bf[off + tid];
                p1 = g_bf[off + tid + 256];
            }
            // A fragments: fp16 hi/lo split of h*c (one 16-row tile)
            unsigned ah[4], al[4];
            {
                float h0 = h_sm[kk * 128 + r0i];
                float h1 = h_sm[kk * 128 + r0i + 8];
                split2h(h0 * cf0.x, h0 * cf0.y, ah[0], al[0]);
                split2h(h1 * cf0.z, h1 * cf0.w, ah[1], al[1]);
                split2h(h0 * cf1.x, h0 * cf1.y, ah[2], al[2]);
                split2h(h1 * cf1.z, h1 * cf1.w, ah[3], al[3]);
            }
            const uint2* bl = &sbuf[cur][lane];
            #pragma unroll
            for (int wt = 0; wt < 16; wt++) {
                uint2 bb = bl[wt * 32];
                mma16816(acc[wt], ah, bb.x, bb.y);   // Ah*Bh
                mma16816(acc[wt], al, bb.x, bb.y);   // Al*Bh
            }
            if (hn) {
                sbuf[nxt][tid]       = p0;
                sbuf[nxt][tid + 256] = p1;
            }
            __syncthreads();
        }
    }

    // D layout: d0,d1 = (row ra, col 2qb,2qb+1); d2,d3 = row ra+8.
    {
        int r0 = base + r0i;
        #pragma unroll
        for (int wt = 0; wt < 16; wt++) {
            int col = wt * 8 + 2 * qb;
            float2* q0 = reinterpret_cast<float2*>(
                g_tp + ((size_t)split * N + r0) * 128 + col);
            float2* q1 = reinterpret_cast<float2*>(
                g_tp + ((size_t)split * N + r0 + 8) * 128 + col);
            *q0 = make_float2(acc[wt][0], acc[wt][1]);
            *q1 = make_float2(acc[wt][2], acc[wt][3]);
        }
    }
}

// ---------------------------------------------------------------------------
// Kernel 4: epilogue — sum 18 splits, LN(128), silu(@om_w1), @om_w2 + b.
// 8 rows per 256-thread block, i-dim split 2-way.
// ---------------------------------------------------------------------------
__global__ __launch_bounds__(256) void out_kernel(const float* __restrict__ lng,
                                                  const float* __restrict__ lnb,
                                                  const float* __restrict__ w1,
                                                  const float* __restrict__ w2,
                                                  const float* __restrict__ bias2,
                                                  float* __restrict__ out, int N) {
    __shared__ float ln_sm[8][128];
    __shared__ float y_sm[8][512];
    __shared__ float part_sm[8][128];
    int tid = threadIdx.x, lane = tid & 31, warp = tid >> 5;
    int rowbase = blockIdx.x * 8;

    {
        int g = rowbase + warp;
        float v[4];
        #pragma unroll
        for (int t = 0; t < 4; t++) {
            int i = lane + 32 * t;
            float s = 0.0f;
            #pragma unroll
            for (int sp = 0; sp < KSPLIT; sp++)
                s += g_tp[((size_t)sp * N + g) * 128 + i];
            v[t] = s;
        }
        float s = v[0] + v[1] + v[2] + v[3];
        #pragma unroll
        for (int o = 16; o; o >>= 1) s += __shfl_xor_sync(0xffffffffu, s, o);
        float mu = s * (1.0f / 128.0f);
        float ss = 0.0f;
        #pragma unroll
        for (int t = 0; t < 4; t++) { float d = v[t] - mu; ss += d * d; }
        #pragma unroll
        for (int o = 16; o; o >>= 1) ss += __shfl_xor_sync(0xffffffffu, ss, o);
        float rstd = rsqrtf(ss * (1.0f / 128.0f) + LN_EPS);
        #pragma unroll
        for (int t = 0; t < 4; t++) {
            int i = lane + 32 * t;
            ln_sm[warp][i] = (v[t] - mu) * rstd * lng[i] + lnb[i];
        }
    }
    __syncthreads();

    int q = tid & 127, hf = tid >> 7;
    float y[8][4];
    #pragma unroll
    for (int r = 0; r < 8; r++)
        #pragma unroll
        for (int cdx = 0; cdx < 4; cdx++) y[r][cdx] = 0.0f;

    const float4* w1v = reinterpret_cast<const float4*>(w1);
    #pragma unroll 8
    for (int ii = 0; ii < 64; ii++) {
        int i = hf * 64 + ii;
        float4 wv = w1v[i * 128 + q];
        #pragma unroll
        for (int r = 0; r < 8; r++) {
            float l = ln_sm[r][i];
            y[r][0] += l * wv.x;
            y[r][1] += l * wv.y;
            y[r][2] += l * wv.z;
            y[r][3] += l * wv.w;
        }
    }
    if (hf == 1) {
        #pragma unroll
        for (int r = 0; r < 8; r++) {
            y_sm[r][q * 4]     = y[r][0];
            y_sm[r][q * 4 + 1] = y[r][1];
            y_sm[r][q * 4 + 2] = y[r][2];
            y_sm[r][q * 4 + 3] = y[r][3];
        }
    }
    __syncthreads();

    if (hf == 0) {
        float4 w2v = reinterpret_cast<const float4*>(w2)[q];
        #pragma unroll
        for (int r = 0; r < 8; r++) {
            float a0 = y[r][0] + y_sm[r][q * 4];
            float a1 = y[r][1] + y_sm[r][q * 4 + 1];
            float a2 = y[r][2] + y_sm[r][q * 4 + 2];
            float a3 = y[r][3] + y_sm[r][q * 4 + 3];
            part_sm[r][q] = silu_f(a0) * w2v.x + silu_f(a1) * w2v.y +
                            silu_f(a2) * w2v.z + silu_f(a3) * w2v.w;
        }
    }
    __syncthreads();

    {
        float s = part_sm[warp][lane] + part_sm[warp][lane + 32] +
                  part_sm[warp][lane + 64] + part_sm[warp][lane + 96];
        #pragma unroll
        for (int o = 16; o; o >>= 1) s += __shfl_xor_sync(0xffffffffu, s, o);
        if (lane == 0) out[rowbase + warp] = s + bias2[0];
    }
}

// ---------------------------------------------------------------------------
extern "C" void kernel_launch(void* const* d_in, const int* in_sizes, int n_in,
                              void* d_out, int out_size) {
    const float* x        = (const float*)d_in[0];
    const float* we_ln_g  = (const float*)d_in[1];
    const float* we_ln_b  = (const float*)d_in[2];
    const float* we_w1    = (const float*)d_in[3];
    const float* we_w2    = (const float*)d_in[4];
    const float* we_b2    = (const float*)d_in[5];
    const float* om_ln_g  = (const float*)d_in[6];
    const float* om_ln_b  = (const float*)d_in[7];
    const float* om_w1    = (const float*)d_in[8];
    const float* om_w2    = (const float*)d_in[9];
    const float* om_b2    = (const float*)d_in[10];

    int N = in_sizes[0] / 64;
    if (N > MAXN) N = MAXN;

    bfrag_kernel<<<NK * NJC, 256>>>(we_w2, we_b2);
    prep_kernel<<<N / 16, 512>>>(x, we_ln_g, we_ln_b, we_w1, N);
    tp_kernel<<<dim3(N / 128, KSPLIT), 256>>>(N);
    out_kernel<<<N / 8, 256>>>(om_ln_g, om_ln_b, om_w1, om_w2, om_b2,
                               (float*)d_out, N);
}

// round 12
// speedup vs baseline: 2.1400x; 1.2736x over previous
#include <cuda_runtime.h>
#include <cuda_fp16.h>

// ---------------------------------------------------------------------------
// WeightedTP via warp-level mma.sync (HMMA, fp16 1-term):
//   tp = A[2048 x 65*272] @ Wsym[65*272 x 128],  A[n,(k,j)] = h[n,k]*c[n,j]
// A and B both single fp16 planes; D = fl16(A)*fl16(B).
// Error: two independent 2^-11 quantizations -> rel_err ~3e-4 << 1e-3
// (B-only measured 2.2e-4 in R10/R11).
// R12: HMMA count halved again vs R11 (2.26M warp-HMMA, floor ~17us).
// ---------------------------------------------------------------------------

#define MAXN 2048
#define NK 65            // 64 hidden + bias row (h=1)
#define NJ 272           // 17 chunks of 16
#define NJC 17
#define KSPLIT 18

#define PATH_COEFF 0.04419417382415922f
#define CG110      0.57735026918962576f
#define LN_EPS     1e-5f

__device__ float g_hT[64 * MAXN];                    // [k][n]
__device__ uint2 g_bf[(size_t)NK * NJC * 16 * 32];   // B frags (fp16) [k][jc][wt][lane]
__device__ float4 g_cf[(size_t)(MAXN/16) * NJC * 32 * 2]; // c frags [mt][jc][lane][2]
__device__ float g_tp[(size_t)KSPLIT * MAXN * 128];

__device__ __forceinline__ float silu_f(float v) { return v / (1.0f + __expf(-v)); }

// pack fp32 pair into one f16x2 (a0 -> low half)
__device__ __forceinline__ unsigned cvt2h(float a0, float a1) {
    __half2 h = __floats2half2_rn(a0, a1);
    return *reinterpret_cast<unsigned*>(&h);
}

__device__ __forceinline__ void mma16816(float* d, const unsigned* a,
                                         unsigned b0, unsigned b1) {
    asm volatile(
        "mma.sync.aligned.m16n8k16.row.col.f32.f16.f16.f32 "
        "{%0,%1,%2,%3}, {%4,%5,%6,%7}, {%8,%9}, {%0,%1,%2,%3};"
        : "+f"(d[0]), "+f"(d[1]), "+f"(d[2]), "+f"(d[3])
        : "r"(a[0]), "r"(a[1]), "r"(a[2]), "r"(a[3]), "r"(b0), "r"(b1));
}

// ---------------------------------------------------------------------------
// Kernel 1: symmetrize + pack B fragments (single fp16 plane), smem-tiled.
// Block per (k, jc).
// ---------------------------------------------------------------------------
__global__ __launch_bounds__(256) void bfrag_kernel(const float* __restrict__ w2,
                                                    const float* __restrict__ b2) {
    __shared__ float sym[16][129];
    int bid = blockIdx.x;
    int k  = bid / NJC;
    int jc = bid % NJC;
    int tid = threadIdx.x;
    const float* src = (k < 64) ? (w2 + (size_t)k * 65536) : b2;

    #pragma unroll
    for (int i = 0; i < 8; i++) {
        int e  = tid + 256 * i;
        int pj = e >> 7;
        int w  = e & 127;
        int j = jc * 16 + pj;
        int p = j / 136, q = j % 136, u = 0;
        while (q >= 16 - u) { q -= 16 - u; u++; }
        int v = u + q;
        float val = src[((p * 256 + u * 16 + v) << 7) + w];
        if (u != v) val += src[((p * 256 + v * 16 + u) << 7) + w];
        sym[pj][w] = val;
    }
    __syncthreads();

    #pragma unroll
    for (int i = 0; i < 2; i++) {
        int s = tid + 256 * i;
        int wt = s >> 5;
        int lane = s & 31;
        int w = wt * 8 + (lane >> 2);
        int jl0 = (lane & 3) * 2;
        uint2 o;
        o.x = cvt2h(sym[jl0][w],     sym[jl0 + 1][w]);
        o.y = cvt2h(sym[jl0 + 8][w], sym[jl0 + 9][w]);
        g_bf[((size_t)(k * NJC + jc) * 16 + wt) * 32 + lane] = o;
    }
}

// ---------------------------------------------------------------------------
// Kernel 2: fused prep — 16 rows/block (warp per row):
// h -> g_hT (transposed), c -> smem -> A-fragment quads g_cf.
// ---------------------------------------------------------------------------
__global__ __launch_bounds__(512) void prep_kernel(const float* __restrict__ x,
                                                   const float* __restrict__ lng,
                                                   const float* __restrict__ lnb,
                                                   const float* __restrict__ w1,
                                                   int N) {
    __shared__ float xs[16][64];
    __shared__ float lns[16][16];
    __shared__ float cs[16 * NJ];
    int tid = threadIdx.x;
    int warp = tid >> 5;
    int lane = tid & 31;
    int mt = blockIdx.x;
    int n = mt * 16 + warp;

    xs[warp][lane]      = x[(size_t)n * 64 + lane];
    xs[warp][lane + 32] = x[(size_t)n * 64 + 32 + lane];
    __syncwarp();

    float f = (lane < 16) ? xs[warp][lane] : 0.0f;
    float s = f;
    #pragma unroll
    for (int o = 16; o; o >>= 1) s += __shfl_xor_sync(0xffffffffu, s, o);
    float mu = s * (1.0f / 16.0f);
    float d = (lane < 16) ? (f - mu) : 0.0f;
    float ss = d * d;
    #pragma unroll
    for (int o = 16; o; o >>= 1) ss += __shfl_xor_sync(0xffffffffu, ss, o);
    float rstd = rsqrtf(ss * (1.0f / 16.0f) + LN_EPS);
    if (lane < 16) lns[warp][lane] = d * rstd * lng[lane] + lnb[lane];
    __syncwarp();

    #pragma unroll
    for (int t = 0; t < 2; t++) {
        int j = lane + 32 * t;
        float acc = 0.0f;
        #pragma unroll
        for (int i = 0; i < 16; i++) acc += lns[warp][i] * w1[i * 64 + j];
        g_hT[(size_t)j * MAXN + n] = silu_f(acc);
    }

    for (int t = lane; t < NJ; t += 32) {
        int p = t / 136, q = t % 136, u = 0;
        while (q >= 16 - u) { q -= 16 - u; u++; }
        int v = u + q;
        float val;
        if (p == 0) {
            val = PATH_COEFF * xs[warp][u] * xs[warp][v];
        } else {
            const float* a = &xs[warp][16 + u * 3];
            const float* b = &xs[warp][16 + v * 3];
            val = PATH_COEFF * CG110 * (a[0] * b[0] + a[1] * b[1] + a[2] * b[2]);
        }
        cs[warp * NJ + t] = val;
    }
    __syncthreads();

    for (int t = tid; t < NJC * 32; t += 512) {
        int l = t & 31;
        int jc = t >> 5;
        int ra = l >> 2;
        int j0 = jc * 16 + (l & 3) * 2;
        const float* c0 = cs + ra * NJ;
        const float* c8 = c0 + 8 * NJ;
        float4 f0, f1;
        f0.x = c0[j0];     f0.y = c0[j0 + 1]; f0.z = c8[j0];     f0.w = c8[j0 + 1];
        f1.x = c0[j0 + 8]; f1.y = c0[j0 + 9]; f1.z = c8[j0 + 8]; f1.w = c8[j0 + 9];
        size_t o = ((size_t)(mt * NJC + jc) * 32 + l) * 2;
        g_cf[o] = f0;
        g_cf[o + 1] = f1;
    }
}

// ---------------------------------------------------------------------------
// Kernel 3: HMMA contraction, fp16 1-term. Grid (N/128, 18), 256 threads,
// 2 CTA/SM. Warp tile 16 rows x 128 cols. B double-buffered in smem.
// ---------------------------------------------------------------------------
__global__ __launch_bounds__(256, 2) void tp_kernel(int N) {
    __shared__ float h_sm[4 * 128];
    __shared__ uint2 sbuf[2][512];           // [buf][wt*32+lane]
    int tid = threadIdx.x;
    int warp = tid >> 5;
    int lane = tid & 31;
    int mblk = blockIdx.x;
    int base = mblk * 128;
    int split = blockIdx.y;
    int k0 = (split * NK) / KSPLIT;
    int k1 = ((split + 1) * NK) / KSPLIT;
    int kc = k1 - k0;

    for (int s = tid; s < kc * 128; s += 256) {
        int k = k0 + (s >> 7);
        h_sm[s] = (k == 64) ? 1.0f : g_hT[(size_t)k * MAXN + base + (s & 127)];
    }
    {   // stage chunk 0 (jc=0, kk=0)
        size_t off = (size_t)(k0 * NJC) * 512;
        sbuf[0][tid]       = g_bf[off + tid];
        sbuf[0][tid + 256] = g_bf[off + tid + 256];
    }
    __syncthreads();

    int ra = lane >> 2;
    int qb = lane & 3;
    int mt = mblk * 8 + warp;      // 16-row tile owned by this warp
    int r0i = warp * 16 + ra;      // row within 128-row CTA tile

    float acc[16][4];
    #pragma unroll
    for (int b = 0; b < 16; b++)
        #pragma unroll
        for (int cdx = 0; cdx < 4; cdx++) acc[b][cdx] = 0.0f;

    const int T = NJC * kc;
    int t = 0;
    for (int jc = 0; jc < NJC; jc++) {
        size_t o = ((size_t)(mt * NJC + jc) * 32 + lane) * 2;
        float4 cf0 = g_cf[o];
        float4 cf1 = g_cf[o + 1];
        for (int kk = 0; kk < kc; kk++, t++) {
            int cur = t & 1, nxt = cur ^ 1;
            bool hn = (t + 1 < T);
            uint2 p0, p1;
            if (hn) {
                int kn = kk + 1, jn = jc;
                if (kn == kc) { kn = 0; jn = jc + 1; }
                size_t off = (size_t)((k0 + kn) * NJC + jn) * 512;
                p0 = g_bf[off + tid];
                p1 = g_bf[off + tid + 256];
            }
            // A fragments: single fp16 plane of h*c
            unsigned ah[4];
            {
                float h0 = h_sm[kk * 128 + r0i];
                float h1 = h_sm[kk * 128 + r0i + 8];
                ah[0] = cvt2h(h0 * cf0.x, h0 * cf0.y);
                ah[1] = cvt2h(h1 * cf0.z, h1 * cf0.w);
                ah[2] = cvt2h(h0 * cf1.x, h0 * cf1.y);
                ah[3] = cvt2h(h1 * cf1.z, h1 * cf1.w);
            }
            const uint2* bl = &sbuf[cur][lane];
            #pragma unroll
            for (int wt = 0; wt < 16; wt++) {
                uint2 bb = bl[wt * 32];
                mma16816(acc[wt], ah, bb.x, bb.y);
            }
            if (hn) {
                sbuf[nxt][tid]       = p0;
                sbuf[nxt][tid + 256] = p1;
            }
            __syncthreads();
        }
    }

    // D layout: d0,d1 = (row ra, col 2qb,2qb+1); d2,d3 = row ra+8.
    {
        int r0 = base + r0i;
        #pragma unroll
        for (int wt = 0; wt < 16; wt++) {
            int col = wt * 8 + 2 * qb;
            float2* q0 = reinterpret_cast<float2*>(
                g_tp + ((size_t)split * N + r0) * 128 + col);
            float2* q1 = reinterpret_cast<float2*>(
                g_tp + ((size_t)split * N + r0 + 8) * 128 + col);
            *q0 = make_float2(acc[wt][0], acc[wt][1]);
            *q1 = make_float2(acc[wt][2], acc[wt][3]);
        }
    }
}

// ---------------------------------------------------------------------------
// Kernel 4: epilogue — sum 18 splits, LN(128), silu(@om_w1), @om_w2 + b.
// 8 rows per 256-thread block, i-dim split 2-way.
// ---------------------------------------------------------------------------
__global__ __launch_bounds__(256) void out_kernel(const float* __restrict__ lng,
                                                  const float* __restrict__ lnb,
                                                  const float* __restrict__ w1,
                                                  const float* __restrict__ w2,
                                                  const float* __restrict__ bias2,
                                                  float* __restrict__ out, int N) {
    __shared__ float ln_sm[8][128];
    __shared__ float y_sm[8][512];
    __shared__ float part_sm[8][128];
    int tid = threadIdx.x, lane = tid & 31, warp = tid >> 5;
    int rowbase = blockIdx.x * 8;

    {
        int g = rowbase + warp;
        float v[4];
        #pragma unroll
        for (int t = 0; t < 4; t++) {
            int i = lane + 32 * t;
            float s = 0.0f;
            #pragma unroll
            for (int sp = 0; sp < KSPLIT; sp++)
                s += g_tp[((size_t)sp * N + g) * 128 + i];
            v[t] = s;
        }
        float s = v[0] + v[1] + v[2] + v[3];
        #pragma unroll
        for (int o = 16; o; o >>= 1) s += __shfl_xor_sync(0xffffffffu, s, o);
        float mu = s * (1.0f / 128.0f);
        float ss = 0.0f;
        #pragma unroll
        for (int t = 0; t < 4; t++) { float d = v[t] - mu; ss += d * d; }
        #pragma unroll
        for (int o = 16; o; o >>= 1) ss += __shfl_xor_sync(0xffffffffu, ss, o);
        float rstd = rsqrtf(ss * (1.0f / 128.0f) + LN_EPS);
        #pragma unroll
        for (int t = 0; t < 4; t++) {
            int i = lane + 32 * t;
            ln_sm[warp][i] = (v[t] - mu) * rstd * lng[i] + lnb[i];
        }
    }
    __syncthreads();

    int q = tid & 127, hf = tid >> 7;
    float y[8][4];
    #pragma unroll
    for (int r = 0; r < 8; r++)
        #pragma unroll
        for (int cdx = 0; cdx < 4; cdx++) y[r][cdx] = 0.0f;

    const float4* w1v = reinterpret_cast<const float4*>(w1);
    #pragma unroll 8
    for (int ii = 0; ii < 64; ii++) {
        int i = hf * 64 + ii;
        float4 wv = w1v[i * 128 + q];
        #pragma unroll
        for (int r = 0; r < 8; r++) {
            float l = ln_sm[r][i];
            y[r][0] += l * wv.x;
            y[r][1] += l * wv.y;
            y[r][2] += l * wv.z;
            y[r][3] += l * wv.w;
        }
    }
    if (hf == 1) {
        #pragma unroll
        for (int r = 0; r < 8; r++) {
            y_sm[r][q * 4]     = y[r][0];
            y_sm[r][q * 4 + 1] = y[r][1];
            y_sm[r][q * 4 + 2] = y[r][2];
            y_sm[r][q * 4 + 3] = y[r][3];
        }
    }
    __syncthreads();

    if (hf == 0) {
        float4 w2v = reinterpret_cast<const float4*>(w2)[q];
        #pragma unroll
        for (int r = 0; r < 8; r++) {
            float a0 = y[r][0] + y_sm[r][q * 4];
            float a1 = y[r][1] + y_sm[r][q * 4 + 1];
            float a2 = y[r][2] + y_sm[r][q * 4 + 2];
            float a3 = y[r][3] + y_sm[r][q * 4 + 3];
            part_sm[r][q] = silu_f(a0) * w2v.x + silu_f(a1) * w2v.y +
                            silu_f(a2) * w2v.z + silu_f(a3) * w2v.w;
        }
    }
    __syncthreads();

    {
        float s = part_sm[warp][lane] + part_sm[warp][lane + 32] +
                  part_sm[warp][lane + 64] + part_sm[warp][lane + 96];
        #pragma unroll
        for (int o = 16; o; o >>= 1) s += __shfl_xor_sync(0xffffffffu, s, o);
        if (lane == 0) out[rowbase + warp] = s + bias2[0];
    }
}

// ---------------------------------------------------------------------------
extern "C" void kernel_launch(void* const* d_in, const int* in_sizes, int n_in,
                              void* d_out, int out_size) {
    const float* x        = (const float*)d_in[0];
    const float* we_ln_g  = (const float*)d_in[1];
    const float* we_ln_b  = (const float*)d_in[2];
    const float* we_w1    = (const float*)d_in[3];
    const float* we_w2    = (const float*)d_in[4];
    const float* we_b2    = (const float*)d_in[5];
    const float* om_ln_g  = (const float*)d_in[6];
    const float* om_ln_b  = (const float*)d_in[7];
    const float* om_w1    = (const float*)d_in[8];
    const float* om_w2    = (const float*)d_in[9];
    const float* om_b2    = (const float*)d_in[10];

    int N = in_sizes[0] / 64;
    if (N > MAXN) N = MAXN;

    bfrag_kernel<<<NK * NJC, 256>>>(we_w2, we_b2);
    prep_kernel<<<N / 16, 512>>>(x, we_ln_g, we_ln_b, we_w1, N);
    tp_kernel<<<dim3(N / 128, KSPLIT), 256>>>(N);
    out_kernel<<<N / 8, 256>>>(om_ln_g, om_ln_b, om_w1, om_w2, om_b2,
                               (float*)d_out, N);
}

// round 13
// speedup vs baseline: 2.1493x; 1.0044x over previous
#include <cuda_runtime.h>
#include <cuda_fp16.h>

// ---------------------------------------------------------------------------
// WeightedTP via warp-level mma.sync (HMMA, fp16 1-term):
//   tp = A[2048 x 68*272] @ Wsym[68*272 x 128],  A[n,(k,j)] = h[n,k]*c[n,j]
// A and B single fp16 planes (rel_err ~3.1e-4, measured 3.06e-4 in R12).
// R13: NK padded 65->68 (zero rows), KSPLIT=17, kc=4 uniform -> full unroll,
//      paired staging (2 chunks per barrier: 61 -> 34 barriers/CTA, A-gen of
//      chunk kk+1 overlaps MMAs of kk between barriers).
// ---------------------------------------------------------------------------

#define MAXN 2048
#define NK 65            // real k rows (64 hidden + bias)
#define NKP 68           // padded (3 zero rows)
#define NJ 272           // 17 chunks of 16
#define NJC 17
#define KSPLIT 17
#define KC 4             // k-chunks per split (uniform)

#define PATH_COEFF 0.04419417382415922f
#define CG110      0.57735026918962576f
#define LN_EPS     1e-5f

__device__ float g_hT[64 * MAXN];                     // [k][n]
__device__ uint2 g_bf[(size_t)NKP * NJC * 16 * 32];   // B frags (fp16) [k][jc][wt][lane]
__device__ float4 g_cf[(size_t)(MAXN/16) * NJC * 32 * 2]; // c frags [mt][jc][lane][2]
__device__ float g_tp[(size_t)KSPLIT * MAXN * 128];

__device__ __forceinline__ float silu_f(float v) { return v / (1.0f + __expf(-v)); }

// pack fp32 pair into one f16x2 (a0 -> low half)
__device__ __forceinline__ unsigned cvt2h(float a0, float a1) {
    __half2 h = __floats2half2_rn(a0, a1);
    return *reinterpret_cast<unsigned*>(&h);
}

__device__ __forceinline__ void mma16816(float* d, const unsigned* a,
                                         unsigned b0, unsigned b1) {
    asm volatile(
        "mma.sync.aligned.m16n8k16.row.col.f32.f16.f16.f32 "
        "{%0,%1,%2,%3}, {%4,%5,%6,%7}, {%8,%9}, {%0,%1,%2,%3};"
        : "+f"(d[0]), "+f"(d[1]), "+f"(d[2]), "+f"(d[3])
        : "r"(a[0]), "r"(a[1]), "r"(a[2]), "r"(a[3]), "r"(b0), "r"(b1));
}

// ---------------------------------------------------------------------------
// Kernel 1: symmetrize + pack B fragments (single fp16 plane), smem-tiled.
// Block per (k, jc); k in [0, NKP) — pad planes (k >= NK) are zero.
// ---------------------------------------------------------------------------
__global__ __launch_bounds__(256) void bfrag_kernel(const float* __restrict__ w2,
                                                    const float* __restrict__ b2) {
    __shared__ float sym[16][129];
    int bid = blockIdx.x;
    int k  = bid / NJC;
    int jc = bid % NJC;
    int tid = threadIdx.x;
    const float* src = (k < 64) ? (w2 + (size_t)k * 65536) : b2;

    #pragma unroll
    for (int i = 0; i < 8; i++) {
        int e  = tid + 256 * i;
        int pj = e >> 7;
        int w  = e & 127;
        float val = 0.0f;
        if (k < NK) {
            int j = jc * 16 + pj;
            int p = j / 136, q = j % 136, u = 0;
            while (q >= 16 - u) { q -= 16 - u; u++; }
            int v = u + q;
            val = src[((p * 256 + u * 16 + v) << 7) + w];
            if (u != v) val += src[((p * 256 + v * 16 + u) << 7) + w];
        }
        sym[pj][w] = val;
    }
    __syncthreads();

    #pragma unroll
    for (int i = 0; i < 2; i++) {
        int s = tid + 256 * i;
        int wt = s >> 5;
        int lane = s & 31;
        int w = wt * 8 + (lane >> 2);
        int jl0 = (lane & 3) * 2;
        uint2 o;
        o.x = cvt2h(sym[jl0][w],     sym[jl0 + 1][w]);
        o.y = cvt2h(sym[jl0 + 8][w], sym[jl0 + 9][w]);
        g_bf[((size_t)(k * NJC + jc) * 16 + wt) * 32 + lane] = o;
    }
}

// ---------------------------------------------------------------------------
// Kernel 2: fused prep — 16 rows/block (warp per row):
// h -> g_hT (transposed), c -> smem -> A-fragment quads g_cf.
// ---------------------------------------------------------------------------
__global__ __launch_bounds__(512) void prep_kernel(const float* __restrict__ x,
                                                   const float* __restrict__ lng,
                                                   const float* __restrict__ lnb,
                                                   const float* __restrict__ w1,
                                                   int N) {
    __shared__ float xs[16][64];
    __shared__ float lns[16][16];
    __shared__ float cs[16 * NJ];
    int tid = threadIdx.x;
    int warp = tid >> 5;
    int lane = tid & 31;
    int mt = blockIdx.x;
    int n = mt * 16 + warp;

    xs[warp][lane]      = x[(size_t)n * 64 + lane];
    xs[warp][lane + 32] = x[(size_t)n * 64 + 32 + lane];
    __syncwarp();

    float f = (lane < 16) ? xs[warp][lane] : 0.0f;
    float s = f;
    #pragma unroll
    for (int o = 16; o; o >>= 1) s += __shfl_xor_sync(0xffffffffu, s, o);
    float mu = s * (1.0f / 16.0f);
    float d = (lane < 16) ? (f - mu) : 0.0f;
    float ss = d * d;
    #pragma unroll
    for (int o = 16; o; o >>= 1) ss += __shfl_xor_sync(0xffffffffu, ss, o);
    float rstd = rsqrtf(ss * (1.0f / 16.0f) + LN_EPS);
    if (lane < 16) lns[warp][lane] = d * rstd * lng[lane] + lnb[lane];
    __syncwarp();

    #pragma unroll
    for (int t = 0; t < 2; t++) {
        int j = lane + 32 * t;
        float acc = 0.0f;
        #pragma unroll
        for (int i = 0; i < 16; i++) acc += lns[warp][i] * w1[i * 64 + j];
        g_hT[(size_t)j * MAXN + n] = silu_f(acc);
    }

    for (int t = lane; t < NJ; t += 32) {
        int p = t / 136, q = t % 136, u = 0;
        while (q >= 16 - u) { q -= 16 - u; u++; }
        int v = u + q;
        float val;
        if (p == 0) {
            val = PATH_COEFF * xs[warp][u] * xs[warp][v];
        } else {
            const float* a = &xs[warp][16 + u * 3];
            const float* b = &xs[warp][16 + v * 3];
            val = PATH_COEFF * CG110 * (a[0] * b[0] + a[1] * b[1] + a[2] * b[2]);
        }
        cs[warp * NJ + t] = val;
    }
    __syncthreads();

    for (int t = tid; t < NJC * 32; t += 512) {
        int l = t & 31;
        int jc = t >> 5;
        int ra = l >> 2;
        int j0 = jc * 16 + (l & 3) * 2;
        const float* c0 = cs + ra * NJ;
        const float* c8 = c0 + 8 * NJ;
        float4 f0, f1;
        f0.x = c0[j0];     f0.y = c0[j0 + 1]; f0.z = c8[j0];     f0.w = c8[j0 + 1];
        f1.x = c0[j0 + 8]; f1.y = c0[j0 + 9]; f1.z = c8[j0 + 8]; f1.w = c8[j0 + 9];
        size_t o = ((size_t)(mt * NJC + jc) * 32 + l) * 2;
        g_cf[o] = f0;
        g_cf[o + 1] = f1;
    }
}

// ---------------------------------------------------------------------------
// Kernel 3: HMMA contraction, fp16 1-term. Grid (N/128, 17), 256 threads,
// 2 CTA/SM. Warp tile 16 rows x 128 cols. Paired staging: 2 k-chunks per
// barrier, double-buffered smem, LDG prefetch one stage ahead.
// ---------------------------------------------------------------------------
__global__ __launch_bounds__(256, 2) void tp_kernel(int N) {
    __shared__ float h_sm[KC * 128];
    __shared__ uint2 sbuf[2][1024];          // [buf][chunk-pair: 2 x 512]
    int tid = threadIdx.x;
    int warp = tid >> 5;
    int lane = tid & 31;
    int mblk = blockIdx.x;
    int base = mblk * 128;
    int split = blockIdx.y;
    int k0 = split * KC;

    for (int s = tid; s < KC * 128; s += 256) {
        int k = k0 + (s >> 7);
        float hv = 0.0f;
        if (k < 64)       hv = g_hT[(size_t)k * MAXN + base + (s & 127)];
        else if (k == 64) hv = 1.0f;
        h_sm[s] = hv;
    }
    {   // preload stage 0 = chunks (kk=0, jc=0) and (kk=1, jc=0)
        size_t o0 = (size_t)((k0 + 0) * NJC) * 512;
        size_t o1 = (size_t)((k0 + 1) * NJC) * 512;
        sbuf[0][tid]             = g_bf[o0 + tid];
        sbuf[0][tid + 256]       = g_bf[o0 + tid + 256];
        sbuf[0][512 + tid]       = g_bf[o1 + tid];
        sbuf[0][512 + tid + 256] = g_bf[o1 + tid + 256];
    }
    __syncthreads();

    int ra = lane >> 2;
    int qb = lane & 3;
    int mt = mblk * 8 + warp;      // 16-row tile owned by this warp
    int r0i = warp * 16 + ra;      // row within 128-row CTA tile

    float acc[16][4];
    #pragma unroll
    for (int b = 0; b < 16; b++)
        #pragma unroll
        for (int cdx = 0; cdx < 4; cdx++) acc[b][cdx] = 0.0f;

    const int NS = NJC * KC / 2;   // 34 stages
    float4 cf0, cf1;
    for (int s = 0; s < NS; s++) {
        int c0  = 2 * s;
        int jc  = c0 >> 2;
        int kk0 = c0 & 3;
        if (kk0 == 0) {
            size_t o = ((size_t)(mt * NJC + jc) * 32 + lane) * 2;
            cf0 = g_cf[o];
            cf1 = g_cf[o + 1];
        }
        uint2 p[4];
        bool hn = (s + 1 < NS);
        if (hn) {   // prefetch next stage (2 chunks)
            int cn = 2 * (s + 1);
            int jn = cn >> 2, kn = cn & 3;
            size_t oa = (size_t)((k0 + kn)     * NJC + jn) * 512;
            size_t ob = (size_t)((k0 + kn + 1) * NJC + jn) * 512;
            p[0] = g_bf[oa + tid];
            p[1] = g_bf[oa + tid + 256];
            p[2] = g_bf[ob + tid];
            p[3] = g_bf[ob + tid + 256];
        }
        const uint2* sb = sbuf[s & 1];
        #pragma unroll
        for (int kp = 0; kp < 2; kp++) {
            int kk = kk0 + kp;
            unsigned ah[4];
            float h0 = h_sm[kk * 128 + r0i];
            float h1 = h_sm[kk * 128 + r0i + 8];
            ah[0] = cvt2h(h0 * cf0.x, h0 * cf0.y);
            ah[1] = cvt2h(h1 * cf0.z, h1 * cf0.w);
            ah[2] = cvt2h(h0 * cf1.x, h0 * cf1.y);
            ah[3] = cvt2h(h1 * cf1.z, h1 * cf1.w);
            const uint2* bl = sb + kp * 512 + lane;
            #pragma unroll
            for (int wt = 0; wt < 16; wt++) {
                uint2 bb = bl[wt * 32];
                mma16816(acc[wt], ah, bb.x, bb.y);
            }
        }
        if (hn) {
            uint2* nb = sbuf[(s + 1) & 1];
            nb[tid]             = p[0];
            nb[tid + 256]       = p[1];
            nb[512 + tid]       = p[2];
            nb[512 + tid + 256] = p[3];
        }
        __syncthreads();
    }

    // D layout: d0,d1 = (row ra, col 2qb,2qb+1); d2,d3 = row ra+8.
    {
        int r0 = base + r0i;
        #pragma unroll
        for (int wt = 0; wt < 16; wt++) {
            int col = wt * 8 + 2 * qb;
            float2* q0 = reinterpret_cast<float2*>(
                g_tp + ((size_t)split * N + r0) * 128 + col);
            float2* q1 = reinterpret_cast<float2*>(
                g_tp + ((size_t)split * N + r0 + 8) * 128 + col);
            *q0 = make_float2(acc[wt][0], acc[wt][1]);
            *q1 = make_float2(acc[wt][2], acc[wt][3]);
        }
    }
}

// ---------------------------------------------------------------------------
// Kernel 4: epilogue — sum 17 splits, LN(128), silu(@om_w1), @om_w2 + b.
// 8 rows per 256-thread block, i-dim split 2-way.
// ---------------------------------------------------------------------------
__global__ __launch_bounds__(256) void out_kernel(const float* __restrict__ lng,
                                                  const float* __restrict__ lnb,
                                                  const float* __restrict__ w1,
                                                  const float* __restrict__ w2,
                                                  const float* __restrict__ bias2,
                                                  float* __restrict__ out, int N) {
    __shared__ float ln_sm[8][128];
    __shared__ float y_sm[8][512];
    __shared__ float part_sm[8][128];
    int tid = threadIdx.x, lane = tid & 31, warp = tid >> 5;
    int rowbase = blockIdx.x * 8;

    {
        int g = rowbase + warp;
        float v[4];
        #pragma unroll
        for (int t = 0; t < 4; t++) {
            int i = lane + 32 * t;
            float s = 0.0f;
            #pragma unroll
            for (int sp = 0; sp < KSPLIT; sp++)
                s += g_tp[((size_t)sp * N + g) * 128 + i];
            v[t] = s;
        }
        float s = v[0] + v[1] + v[2] + v[3];
        #pragma unroll
        for (int o = 16; o; o >>= 1) s += __shfl_xor_sync(0xffffffffu, s, o);
        float mu = s * (1.0f / 128.0f);
        float ss = 0.0f;
        #pragma unroll
        for (int t = 0; t < 4; t++) { float d = v[t] - mu; ss += d * d; }
        #pragma unroll
        for (int o = 16; o; o >>= 1) ss += __shfl_xor_sync(0xffffffffu, ss, o);
        float rstd = rsqrtf(ss * (1.0f / 128.0f) + LN_EPS);
        #pragma unroll
        for (int t = 0; t < 4; t++) {
            int i = lane + 32 * t;
            ln_sm[warp][i] = (v[t] - mu) * rstd * lng[i] + lnb[i];
        }
    }
    __syncthreads();

    int q = tid & 127, hf = tid >> 7;
    float y[8][4];
    #pragma unroll
    for (int r = 0; r < 8; r++)
        #pragma unroll
        for (int cdx = 0; cdx < 4; cdx++) y[r][cdx] = 0.0f;

    const float4* w1v = reinterpret_cast<const float4*>(w1);
    #pragma unroll 8
    for (int ii = 0; ii < 64; ii++) {
        int i = hf * 64 + ii;
        float4 wv = w1v[i * 128 + q];
        #pragma unroll
        for (int r = 0; r < 8; r++) {
            float l = ln_sm[r][i];
            y[r][0] += l * wv.x;
            y[r][1] += l * wv.y;
            y[r][2] += l * wv.z;
            y[r][3] += l * wv.w;
        }
    }
    if (hf == 1) {
        #pragma unroll
        for (int r = 0; r < 8; r++) {
            y_sm[r][q * 4]     = y[r][0];
            y_sm[r][q * 4 + 1] = y[r][1];
            y_sm[r][q * 4 + 2] = y[r][2];
            y_sm[r][q * 4 + 3] = y[r][3];
        }
    }
    __syncthreads();

    if (hf == 0) {
        float4 w2v = reinterpret_cast<const float4*>(w2)[q];
        #pragma unroll
        for (int r = 0; r < 8; r++) {
            float a0 = y[r][0] + y_sm[r][q * 4];
            float a1 = y[r][1] + y_sm[r][q * 4 + 1];
            float a2 = y[r][2] + y_sm[r][q * 4 + 2];
            float a3 = y[r][3] + y_sm[r][q * 4 + 3];
            part_sm[r][q] = silu_f(a0) * w2v.x + silu_f(a1) * w2v.y +
                            silu_f(a2) * w2v.z + silu_f(a3) * w2v.w;
        }
    }
    __syncthreads();

    {
        float s = part_sm[warp][lane] + part_sm[warp][lane + 32] +
                  part_sm[warp][lane + 64] + part_sm[warp][lane + 96];
        #pragma unroll
        for (int o = 16; o; o >>= 1) s += __shfl_xor_sync(0xffffffffu, s, o);
        if (lane == 0) out[rowbase + warp] = s + bias2[0];
    }
}

// ---------------------------------------------------------------------------
extern "C" void kernel_launch(void* const* d_in, const int* in_sizes, int n_in,
                              void* d_out, int out_size) {
    const float* x        = (const float*)d_in[0];
    const float* we_ln_g  = (const float*)d_in[1];
    const float* we_ln_b  = (const float*)d_in[2];
    const float* we_w1    = (const float*)d_in[3];
    const float* we_w2    = (const float*)d_in[4];
    const float* we_b2    = (const float*)d_in[5];
    const float* om_ln_g  = (const float*)d_in[6];
    const float* om_ln_b  = (const float*)d_in[7];
    const float* om_w1    = (const float*)d_in[8];
    const float* om_w2    = (const float*)d_in[9];
    const float* om_b2    = (const float*)d_in[10];

    int N = in_sizes[0] / 64;
    if (N > MAXN) N = MAXN;

    bfrag_kernel<<<NKP * NJC, 256>>>(we_w2, we_b2);
    prep_kernel<<<N / 16, 512>>>(x, we_ln_g, we_ln_b, we_w1, N);
    tp_kernel<<<dim3(N / 128, KSPLIT), 256>>>(N);
    out_kernel<<<N / 8, 256>>>(om_ln_g, om_ln_b, om_w1, om_w2, om_b2,
                               (float*)d_out, N);
}